// round 3
// baseline (speedup 1.0000x reference)
#include <cuda_runtime.h>
#include <math.h>
#include <stdint.h>

#define HIDDEN 1024
#define STATE  64
#define INTER  4096
#define BATCH  4
#define SEQ    2048
#define ROWS   (BATCH*SEQ)   // 8192
#define NCHUNK 32
#define CLEN   64            // NCHUNK*CLEN == SEQ

// ---------------- scratch (static device allocations; no cudaMalloc) ----------------
__device__ float g_hn1[ROWS*HIDDEN];
__device__ float g_h  [ROWS*HIDDEN];
__device__ float g_hn2[ROWS*HIDDEN];
__device__ float g_U  [ROWS*STATE];
__device__ float g_S  [ROWS*STATE];
__device__ float g_act[ROWS*INTER];
__device__ float g_Bbar[STATE*HIDDEN];
__device__ float g_AbT [STATE*STATE];     // AbT[j*64+i] = A_bar[i][j]
__device__ float g_A64T[STATE*STATE];     // A_bar^64, same layout
__device__ float g_tail [BATCH*NCHUNK*STATE];
__device__ float g_carry[BATCH*NCHUNK*STATE];
__device__ float g_wg[INTER*HIDDEN];      // tf32-rounded weights
__device__ float g_wu[INTER*HIDDEN];
__device__ float g_wd[HIDDEN*INTER];

__device__ __forceinline__ float to_tf32(float x) {
    uint32_t u;
    asm("cvt.rna.tf32.f32 %0, %1;" : "=r"(u) : "f"(x));
    return __uint_as_float(u);
}

// ---------------- prep (fused): dt, Bbar, expm(A*mean_dt), A_bar^64 ----------------
// Matmul pattern: thread owns (row i, 16 cols j0..j0+15). Per l: 1 broadcast LDS of
// T[i][l] + 4x LDS.128 of M[l][j0..j0+15] (8-way lane broadcast) + 16 FMA.
__global__ void prep_kernel(const float* __restrict__ A,
                            const float* __restrict__ B,
                            const float* __restrict__ log_dt)
{
    __shared__ __align__(16) float Mm[4096];
    __shared__ __align__(16) float Tb[4096];
    __shared__ __align__(16) float Rb[4096];
    int tid = threadIdx.x;                 // 256

    // phase 1: dt = exp(log_dt) in Tb[0..1024), reduction in Rb[0..256)
    float local = 0.f;
    for (int e = tid; e < HIDDEN; e += 256) {
        float d = expf(log_dt[e]);
        Tb[e] = d;
        local += d;
    }
    Rb[tid] = local;
    __syncthreads();
    for (int s = 128; s > 0; s >>= 1) {
        if (tid < s) Rb[tid] += Rb[tid + s];
        __syncthreads();
    }
    float md = Rb[0] * (1.f / HIDDEN);

    for (int e = tid; e < STATE*HIDDEN; e += 256)
        g_Bbar[e] = B[e] * Tb[e & (HIDDEN - 1)];
    __syncthreads();

    // phase 2: A_bar = expm(A*md), 6-term Taylor (||A*md|| ~ 3e-3 -> exact)
    int i  = tid >> 2;
    int j0 = (tid & 3) << 4;

    for (int e = tid; e < 4096; e += 256) {
        float m = A[e] * md;
        Mm[e] = m; Tb[e] = m;
        Rb[e] = m + ((e >> 6) == (e & 63) ? 1.f : 0.f);
    }
    __syncthreads();

    for (int k = 2; k <= 6; k++) {
        float v[16];
        #pragma unroll
        for (int c = 0; c < 16; c++) v[c] = 0.f;
        #pragma unroll 4
        for (int l = 0; l < 64; l++) {
            float t = Tb[i*64 + l];
            const float4* mr = (const float4*)&Mm[l*64 + j0];
            float4 m0 = mr[0], m1 = mr[1], m2 = mr[2], m3 = mr[3];
            v[0]+=t*m0.x;  v[1]+=t*m0.y;  v[2]+=t*m0.z;  v[3]+=t*m0.w;
            v[4]+=t*m1.x;  v[5]+=t*m1.y;  v[6]+=t*m1.z;  v[7]+=t*m1.w;
            v[8]+=t*m2.x;  v[9]+=t*m2.y;  v[10]+=t*m2.z; v[11]+=t*m2.w;
            v[12]+=t*m3.x; v[13]+=t*m3.y; v[14]+=t*m3.z; v[15]+=t*m3.w;
        }
        float inv = 1.f / (float)k;
        __syncthreads();
        #pragma unroll
        for (int c = 0; c < 16; c++) {
            float nv = v[c] * inv;
            Tb[i*64 + j0 + c] = nv;
            Rb[i*64 + j0 + c] += nv;
        }
        __syncthreads();
    }

    #pragma unroll
    for (int c = 0; c < 16; c++)
        g_AbT[(j0 + c)*64 + i] = Rb[i*64 + j0 + c];   // transposed

    // phase 3: A64 = A_bar^64 via 6 squarings of Rb (in place, sync-separated)
    for (int s = 0; s < 6; s++) {
        float v[16];
        #pragma unroll
        for (int c = 0; c < 16; c++) v[c] = 0.f;
        #pragma unroll 4
        for (int l = 0; l < 64; l++) {
            float t = Rb[i*64 + l];
            const float4* mr = (const float4*)&Rb[l*64 + j0];
            float4 m0 = mr[0], m1 = mr[1], m2 = mr[2], m3 = mr[3];
            v[0]+=t*m0.x;  v[1]+=t*m0.y;  v[2]+=t*m0.z;  v[3]+=t*m0.w;
            v[4]+=t*m1.x;  v[5]+=t*m1.y;  v[6]+=t*m1.z;  v[7]+=t*m1.w;
            v[8]+=t*m2.x;  v[9]+=t*m2.y;  v[10]+=t*m2.z; v[11]+=t*m2.w;
            v[12]+=t*m3.x; v[13]+=t*m3.y; v[14]+=t*m3.z; v[15]+=t*m3.w;
        }
        __syncthreads();
        #pragma unroll
        for (int c = 0; c < 16; c++) Rb[i*64 + j0 + c] = v[c];
        __syncthreads();
    }
    #pragma unroll
    for (int c = 0; c < 16; c++)
        g_A64T[(j0 + c)*64 + i] = Rb[i*64 + j0 + c];
}

// ---------------- rmsnorm (optionally rounds output to tf32) ----------------
__global__ void rmsnorm_kernel(const float* __restrict__ x,
                               const float* __restrict__ w,
                               float* __restrict__ out, int round_tf32)
{
    int row = blockIdx.x;
    const float4* xr = (const float4*)(x + (size_t)row * HIDDEN);
    float4 v = xr[threadIdx.x];
    float ss = v.x*v.x + v.y*v.y + v.z*v.z + v.w*v.w;
    #pragma unroll
    for (int o = 16; o > 0; o >>= 1) ss += __shfl_down_sync(0xffffffffu, ss, o);
    __shared__ float wr[8];
    __shared__ float sc;
    if ((threadIdx.x & 31) == 0) wr[threadIdx.x >> 5] = ss;
    __syncthreads();
    if (threadIdx.x == 0) {
        float t = 0.f;
        #pragma unroll
        for (int k = 0; k < 8; k++) t += wr[k];
        sc = rsqrtf(t * (1.f / HIDDEN) + 1e-6f);
    }
    __syncthreads();
    float s = sc;
    const float4* ww = (const float4*)w;
    float4 wv = ww[threadIdx.x];
    float4 o4 = make_float4(v.x*s*wv.x, v.y*s*wv.y, v.z*s*wv.z, v.w*s*wv.w);
    if (round_tf32) {
        o4.x = to_tf32(o4.x); o4.y = to_tf32(o4.y);
        o4.z = to_tf32(o4.z); o4.w = to_tf32(o4.w);
    }
    ((float4*)(out + (size_t)row * HIDDEN))[threadIdx.x] = o4;
}

// ---------------- weight rounding to tf32 ----------------
__global__ void round_kernel(const float* __restrict__ in, float* __restrict__ out, int n)
{
    int i = blockIdx.x * 256 + threadIdx.x;
    int stride = gridDim.x * 256;
    for (; i < n; i += stride) out[i] = to_tf32(in[i]);
}

// ---------------- chunked scan ----------------
__global__ void local_scan_kernel()
{
    int c = blockIdx.x, b = blockIdx.y;
    const float* u = g_U + (size_t)(b*SEQ + c*CLEN) * STATE;
    float* sout    = g_S + (size_t)(b*SEQ + c*CLEN) * STATE;

    __shared__ float st[64];
    __shared__ float part[4][64];
    __shared__ float ub[CLEN*64];

    int tid = threadIdx.x;
    int i = tid & 63, p = tid >> 6;

    float a[16];
    #pragma unroll
    for (int jj = 0; jj < 16; jj++) a[jj] = g_AbT[(p*16 + jj)*64 + i];

    for (int e = tid; e < CLEN*64; e += 256) ub[e] = u[e];
    if (tid < 64) st[i] = 0.f;
    __syncthreads();

    for (int t = 0; t < CLEN; t++) {
        float acc = 0.f;
        #pragma unroll
        for (int jj = 0; jj < 16; jj++) acc += a[jj] * st[p*16 + jj];
        part[p][i] = acc;
        __syncthreads();
        if (tid < 64) {
            float v = part[0][i] + part[1][i] + part[2][i] + part[3][i] + ub[t*64 + i];
            st[i] = v;
            sout[(size_t)t*STATE + i] = v;
        }
        __syncthreads();
    }
    if (tid < 64) g_tail[(size_t)(b*NCHUNK + c)*STATE + i] = st[i];
}

__global__ void carry_kernel()
{
    int b = blockIdx.x;
    __shared__ float st[64];
    __shared__ float part[4][64];
    __shared__ float tails[NCHUNK*64];

    int tid = threadIdx.x;
    int i = tid & 63, p = tid >> 6;

    float a[16];
    #pragma unroll
    for (int jj = 0; jj < 16; jj++) a[jj] = g_A64T[(p*16 + jj)*64 + i];

    for (int e = tid; e < NCHUNK*64; e += 256)
        tails[e] = g_tail[(size_t)b*NCHUNK*STATE + e];
    if (tid < 64) {
        st[i] = 0.f;
        g_carry[(size_t)b*NCHUNK*STATE + i] = 0.f;
    }
    __syncthreads();

    for (int c = 1; c < NCHUNK; c++) {
        float acc = 0.f;
        #pragma unroll
        for (int jj = 0; jj < 16; jj++) acc += a[jj] * st[p*16 + jj];
        part[p][i] = acc;
        __syncthreads();
        if (tid < 64) {
            float v = part[0][i] + part[1][i] + part[2][i] + part[3][i]
                    + tails[(c-1)*64 + i];
            st[i] = v;
            g_carry[(size_t)(b*NCHUNK + c)*STATE + i] = v;
        }
        __syncthreads();
    }
}

__global__ void fixup_kernel()
{
    int c = blockIdx.x, b = blockIdx.y;
    float* sout = g_S + (size_t)(b*SEQ + c*CLEN) * STATE;

    __shared__ float st[64];
    __shared__ float part[4][64];

    int tid = threadIdx.x;
    int i = tid & 63, p = tid >> 6;

    float a[16];
    #pragma unroll
    for (int jj = 0; jj < 16; jj++) a[jj] = g_AbT[(p*16 + jj)*64 + i];

    if (tid < 64) st[i] = g_carry[(size_t)(b*NCHUNK + c)*STATE + i];
    __syncthreads();

    for (int t = 0; t < CLEN; t++) {
        float acc = 0.f;
        #pragma unroll
        for (int jj = 0; jj < 16; jj++) acc += a[jj] * st[p*16 + jj];
        part[p][i] = acc;
        __syncthreads();
        if (tid < 64) {
            float v = part[0][i] + part[1][i] + part[2][i] + part[3][i];
            st[i] = v;
            sout[(size_t)t*STATE + i] += v;
        }
        __syncthreads();
    }
}

// ---------------- SIMT SGEMM (small GEMMs + mode-1 epilogue) ----------------
#define BM 64
#define BN 128
#define BK 16
__global__ void __launch_bounds__(256) sgemm_kernel(
    const float* __restrict__ A, const float* __restrict__ Bm,
    int M, int N, int K, float* __restrict__ out, int mode,
    const float* __restrict__ res, const float* __restrict__ extra,
    const float* __restrict__ dvec)
{
    __shared__ float As[BK][BM];
    __shared__ float Bs[BK][BN];
    int tid = threadIdx.x;
    int m0 = blockIdx.y * BM, n0 = blockIdx.x * BN;

    int lr = tid >> 2;
    int lk = (tid & 3) * 4;
    const float* Ap  = A  + (size_t)(m0 + lr) * K + lk;
    int bn1 = n0 + lr, bn2 = n0 + lr + 64;
    const float* Bp1 = Bm + (size_t)bn1 * K + lk;
    const float* Bp2 = Bm + (size_t)bn2 * K + lk;
    bool v1 = bn1 < N, v2 = bn2 < N;

    int wid = tid >> 5, lane = tid & 31;
    float acc[8][4];
    #pragma unroll
    for (int r = 0; r < 8; r++)
        #pragma unroll
        for (int c = 0; c < 4; c++) acc[r][c] = 0.f;

    const float4 z4 = make_float4(0.f, 0.f, 0.f, 0.f);
    for (int k0 = 0; k0 < K; k0 += BK) {
        float4 av = *(const float4*)(Ap + k0);
        float4 b1 = v1 ? *(const float4*)(Bp1 + k0) : z4;
        float4 b2 = v2 ? *(const float4*)(Bp2 + k0) : z4;
        As[lk+0][lr] = av.x; As[lk+1][lr] = av.y; As[lk+2][lr] = av.z; As[lk+3][lr] = av.w;
        Bs[lk+0][lr] = b1.x; Bs[lk+1][lr] = b1.y; Bs[lk+2][lr] = b1.z; Bs[lk+3][lr] = b1.w;
        Bs[lk+0][lr+64] = b2.x; Bs[lk+1][lr+64] = b2.y; Bs[lk+2][lr+64] = b2.z; Bs[lk+3][lr+64] = b2.w;
        __syncthreads();
        #pragma unroll
        for (int kk = 0; kk < BK; kk++) {
            float4 b  = *(const float4*)&Bs[kk][lane*4];
            float4 a0 = *(const float4*)&As[kk][wid*8];
            float4 a1 = *(const float4*)&As[kk][wid*8 + 4];
            float ar[8] = {a0.x,a0.y,a0.z,a0.w,a1.x,a1.y,a1.z,a1.w};
            float br[4] = {b.x,b.y,b.z,b.w};
            #pragma unroll
            for (int r = 0; r < 8; r++)
                #pragma unroll
                for (int c = 0; c < 4; c++)
                    acc[r][c] += ar[r] * br[c];
        }
        __syncthreads();
    }

    #pragma unroll
    for (int r = 0; r < 8; r++) {
        int row = m0 + wid*8 + r;
        #pragma unroll
        for (int c = 0; c < 4; c++) {
            int col = n0 + lane*4 + c;
            if (col < N) {
                size_t idx = (size_t)row * N + col;
                float v = acc[r][c];
                if (mode == 1) v = res[idx] + v + dvec[col]*extra[idx];
                out[idx] = v;
            }
        }
    }
}

// ---------------- tf32 tensor-core GEMM v2: C = A[M,K] @ B[N,K]^T ----------------
// CTA tile 256x128x32, 8 warps (4x2), warp tile 64x64 (4 mt x 8 nt of m16n8k8),
// 3-stage cp.async pipeline (144 KB dynamic smem, 1 CTA/SM).
__device__ __forceinline__ void cp16(float* s, const float* g) {
    uint32_t sa = (uint32_t)__cvta_generic_to_shared(s);
    asm volatile("cp.async.cg.shared.global [%0], [%1], 16;\n" :: "r"(sa), "l"(g));
}
__device__ __forceinline__ void mma_tf32(float* d,
    uint32_t a0, uint32_t a1, uint32_t a2, uint32_t a3, uint32_t b0, uint32_t b1)
{
    asm volatile(
        "mma.sync.aligned.m16n8k8.row.col.f32.tf32.tf32.f32 "
        "{%0,%1,%2,%3}, {%4,%5,%6,%7}, {%8,%9}, {%0,%1,%2,%3};\n"
        : "+f"(d[0]), "+f"(d[1]), "+f"(d[2]), "+f"(d[3])
        : "r"(a0), "r"(a1), "r"(a2), "r"(a3), "r"(b0), "r"(b1));
}

#define GM 256
#define GN 128
#define STG 12288   // floats per stage: A 256*32 + B 128*32

// modes: 0 plain; 2 out = tf32(silu(res)*acc); 3 out = res + acc
__global__ void __launch_bounds__(256) gemm_tf32(
    const float* __restrict__ A, const float* __restrict__ Bm,
    int M, int N, int K, float* __restrict__ out, int mode,
    const float* __restrict__ res)
{
    extern __shared__ __align__(16) float sm[];
    int tid = threadIdx.x;
    int m0 = blockIdx.y * GM, n0 = blockIdx.x * GN;

    int lrow = tid >> 3, k4 = tid & 7;     // loader: 32 rows x 8 float4-cols
    const float* Ag = A  + (size_t)(m0 + lrow) * K + k4*4;
    const float* Bg = Bm + (size_t)(n0 + lrow) * K + k4*4;

    int lane = tid & 31, warp = tid >> 5;
    int wm = warp & 3, wn = warp >> 2;     // 4 x 2 warp grid, warp tile 64x64
    int gid = lane >> 2, tig = lane & 3;

    float acc[4][8][4];
    #pragma unroll
    for (int mt = 0; mt < 4; mt++)
        #pragma unroll
        for (int nt = 0; nt < 8; nt++)
            #pragma unroll
            for (int r = 0; r < 4; r++) acc[mt][nt][r] = 0.f;

    int NT = K >> 5;

    #define LOAD_STAGE(kt, s) do {                                            \
        float* As_ = sm + (s)*STG;                                            \
        float* Bs_ = As_ + 8192;                                              \
        int k0_ = (kt) << 5;                                                  \
        int sw_ = k4 ^ (lrow & 7);                                            \
        _Pragma("unroll")                                                     \
        for (int p_ = 0; p_ < 8; p_++)                                        \
            cp16(As_ + ((lrow + p_*32)*8 + sw_)*4, Ag + (size_t)p_*32*K + k0_); \
        _Pragma("unroll")                                                     \
        for (int p_ = 0; p_ < 4; p_++)                                        \
            cp16(Bs_ + ((lrow + p_*32)*8 + sw_)*4, Bg + (size_t)p_*32*K + k0_); \
        asm volatile("cp.async.commit_group;\n");                             \
    } while (0)

    LOAD_STAGE(0, 0);
    if (NT > 1) LOAD_STAGE(1, 1);
    if (NT > 2) LOAD_STAGE(2, 2);

    int st = 0;
    for (int kt = 0; kt < NT; kt++) {
        if (kt + 2 < NT)      asm volatile("cp.async.wait_group 2;\n");
        else if (kt + 1 < NT) asm volatile("cp.async.wait_group 1;\n");
        else                  asm volatile("cp.async.wait_group 0;\n");
        __syncthreads();

        const float* As = sm + st*STG;
        const float* Bs = As + 8192;

        #pragma unroll
        for (int ks = 0; ks < 4; ks++) {
            uint32_t bf[8][2];
            #pragma unroll
            for (int nt = 0; nt < 8; nt++) {
                int c = wn*64 + nt*8 + gid;
                int sw = c & 7;
                bf[nt][0] = __float_as_uint(Bs[c*32 + (((2*ks)   ^ sw) << 2) + tig]);
                bf[nt][1] = __float_as_uint(Bs[c*32 + (((2*ks+1) ^ sw) << 2) + tig]);
            }
            #pragma unroll
            for (int mt = 0; mt < 4; mt++) {
                int r = wm*64 + mt*16 + gid;
                int r8 = r + 8;
                uint32_t a0 = __float_as_uint(As[r *32 + (((2*ks)   ^ (r  & 7)) << 2) + tig]);
                uint32_t a1 = __float_as_uint(As[r8*32 + (((2*ks)   ^ (r8 & 7)) << 2) + tig]);
                uint32_t a2 = __float_as_uint(As[r *32 + (((2*ks+1) ^ (r  & 7)) << 2) + tig]);
                uint32_t a3 = __float_as_uint(As[r8*32 + (((2*ks+1) ^ (r8 & 7)) << 2) + tig]);
                #pragma unroll
                for (int nt = 0; nt < 8; nt++)
                    mma_tf32(acc[mt][nt], a0, a1, a2, a3, bf[nt][0], bf[nt][1]);
            }
        }
        __syncthreads();
        if (kt + 3 < NT) LOAD_STAGE(kt + 3, st);   // stage just freed
        st = (st == 2) ? 0 : st + 1;
    }
    #undef LOAD_STAGE

    // epilogue
    #pragma unroll
    for (int mt = 0; mt < 4; mt++) {
        #pragma unroll
        for (int nt = 0; nt < 8; nt++) {
            int row0 = m0 + wm*64 + mt*16 + gid;
            int col0 = n0 + wn*64 + nt*8 + tig*2;
            #pragma unroll
            for (int half = 0; half < 2; half++) {
                int row = row0 + half*8;
                size_t idx = (size_t)row * N + col0;
                float v0 = acc[mt][nt][half*2 + 0];
                float v1 = acc[mt][nt][half*2 + 1];
                if (mode == 2) {
                    float2 g2 = *(const float2*)(res + idx);
                    v0 = to_tf32(v0 * (g2.x / (1.f + expf(-g2.x))));
                    v1 = to_tf32(v1 * (g2.y / (1.f + expf(-g2.y))));
                } else if (mode == 3) {
                    float2 r2 = *(const float2*)(res + idx);
                    v0 += r2.x;
                    v1 += r2.y;
                }
                *(float2*)(out + idx) = make_float2(v0, v1);
            }
        }
    }
}

// ---------------- launch ----------------
extern "C" void kernel_launch(void* const* d_in, const int* in_sizes, int n_in,
                              void* d_out, int out_size)
{
    const float* x      = (const float*)d_in[0];
    const float* A      = (const float*)d_in[1];
    const float* B      = (const float*)d_in[2];
    const float* C      = (const float*)d_in[3];
    const float* D      = (const float*)d_in[4];
    const float* log_dt = (const float*)d_in[5];
    const float* w_gate = (const float*)d_in[6];
    const float* w_up   = (const float*)d_in[7];
    const float* w_down = (const float*)d_in[8];
    const float* ln1    = (const float*)d_in[9];
    const float* ln2    = (const float*)d_in[10];
    float* out = (float*)d_out;

    float *hn1, *h, *hn2, *U, *S, *act, *Bbar, *wg, *wu, *wd;
    cudaGetSymbolAddress((void**)&hn1,  g_hn1);
    cudaGetSymbolAddress((void**)&h,    g_h);
    cudaGetSymbolAddress((void**)&hn2,  g_hn2);
    cudaGetSymbolAddress((void**)&U,    g_U);
    cudaGetSymbolAddress((void**)&S,    g_S);
    cudaGetSymbolAddress((void**)&act,  g_act);
    cudaGetSymbolAddress((void**)&Bbar, g_Bbar);
    cudaGetSymbolAddress((void**)&wg,   g_wg);
    cudaGetSymbolAddress((void**)&wu,   g_wu);
    cudaGetSymbolAddress((void**)&wd,   g_wd);

    const int DSMEM = 3 * STG * 4;   // 147456 bytes
    cudaFuncSetAttribute(gemm_tf32, cudaFuncAttributeMaxDynamicSharedMemorySize, DSMEM);

    // weight rounding (independent of SSM path)
    round_kernel<<<512, 256>>>(w_gate, wg, INTER*HIDDEN);
    round_kernel<<<512, 256>>>(w_up,   wu, INTER*HIDDEN);
    round_kernel<<<512, 256>>>(w_down, wd, HIDDEN*INTER);

    // SSM path
    prep_kernel<<<1, 256>>>(A, B, log_dt);
    rmsnorm_kernel<<<ROWS, 256>>>(x, ln1, hn1, 0);
    sgemm_kernel<<<dim3(1, ROWS/BM), 256>>>(hn1, Bbar, ROWS, STATE, HIDDEN,
                                            U, 0, nullptr, nullptr, nullptr);
    local_scan_kernel<<<dim3(NCHUNK, BATCH), 256>>>();
    carry_kernel<<<BATCH, 256>>>();
    fixup_kernel<<<dim3(NCHUNK, BATCH), 256>>>();
    // h = x + S @ C^T + D*hn1
    sgemm_kernel<<<dim3(HIDDEN/BN, ROWS/BM), 256>>>(S, C, ROWS, HIDDEN, STATE,
                                                    h, 1, x, hn1, D);
    // FFN (tf32 tensor cores)
    rmsnorm_kernel<<<ROWS, 256>>>(h, ln2, hn2, 1);
    gemm_tf32<<<dim3(INTER/GN, ROWS/GM), 256, DSMEM>>>(hn2, wg, ROWS, INTER, HIDDEN,
                                                       act, 0, nullptr);
    gemm_tf32<<<dim3(INTER/GN, ROWS/GM), 256, DSMEM>>>(hn2, wu, ROWS, INTER, HIDDEN,
                                                       act, 2, act);
    gemm_tf32<<<dim3(HIDDEN/GN, ROWS/GM), 256, DSMEM>>>(act, wd, ROWS, HIDDEN, INTER,
                                                        out, 3, h);
}

// round 4
// speedup vs baseline: 1.1095x; 1.1095x over previous
#include <cuda_runtime.h>
#include <math.h>
#include <stdint.h>

#define HIDDEN 1024
#define STATE  64
#define INTER  4096
#define BATCH  4
#define SEQ    2048
#define ROWS   (BATCH*SEQ)   // 8192
#define NCHUNK 32
#define CLEN   64            // NCHUNK*CLEN == SEQ

// ---------------- scratch (static device allocations; no cudaMalloc) ----------------
__device__ float g_hn1[ROWS*HIDDEN];
__device__ float g_h  [ROWS*HIDDEN];
__device__ float g_hn2[ROWS*HIDDEN];
__device__ float g_U  [ROWS*STATE];
__device__ float g_S  [ROWS*STATE];
__device__ float g_act[ROWS*INTER];
__device__ float g_Bbar[STATE*HIDDEN];
__device__ float g_AbT [STATE*STATE];     // AbT[j*64+i] = A_bar[i][j]
__device__ float g_A64T[STATE*STATE];     // A_bar^64, same layout
__device__ float g_tail [BATCH*NCHUNK*STATE];
__device__ float g_carry[BATCH*NCHUNK*STATE];
__device__ float g_wg[INTER*HIDDEN];      // tf32-rounded weights
__device__ float g_wu[INTER*HIDDEN];
__device__ float g_wd[HIDDEN*INTER];

__device__ __forceinline__ float to_tf32(float x) {
    uint32_t u;
    asm("cvt.rna.tf32.f32 %0, %1;" : "=r"(u) : "f"(x));
    return __uint_as_float(u);
}

// 64x64 smem matmul core: thread (i = tid>>2, j0 = (tid&3)*16) computes
// v[0..15] = sum_l X[i][l] * Y[l][j0..j0+15].
// k-blocked by 4: 17 independent float4 LDS up front, then 64 FMAs -> deep MLP.
__device__ __forceinline__ void mm64(const float* __restrict__ X,
                                     const float* __restrict__ Y,
                                     int i, int j0, float v[16])
{
    #pragma unroll
    for (int c = 0; c < 16; c++) v[c] = 0.f;
    #pragma unroll 4
    for (int lb = 0; lb < 64; lb += 4) {
        float4 t = *(const float4*)&X[i*64 + lb];
        float4 m0 = *(const float4*)&Y[(lb+0)*64 + j0];
        float4 m1 = *(const float4*)&Y[(lb+0)*64 + j0 + 4];
        float4 m2 = *(const float4*)&Y[(lb+0)*64 + j0 + 8];
        float4 m3 = *(const float4*)&Y[(lb+0)*64 + j0 + 12];
        float4 n0 = *(const float4*)&Y[(lb+1)*64 + j0];
        float4 n1 = *(const float4*)&Y[(lb+1)*64 + j0 + 4];
        float4 n2 = *(const float4*)&Y[(lb+1)*64 + j0 + 8];
        float4 n3 = *(const float4*)&Y[(lb+1)*64 + j0 + 12];
        float4 p0 = *(const float4*)&Y[(lb+2)*64 + j0];
        float4 p1 = *(const float4*)&Y[(lb+2)*64 + j0 + 4];
        float4 p2 = *(const float4*)&Y[(lb+2)*64 + j0 + 8];
        float4 p3 = *(const float4*)&Y[(lb+2)*64 + j0 + 12];
        float4 q0 = *(const float4*)&Y[(lb+3)*64 + j0];
        float4 q1 = *(const float4*)&Y[(lb+3)*64 + j0 + 4];
        float4 q2 = *(const float4*)&Y[(lb+3)*64 + j0 + 8];
        float4 q3 = *(const float4*)&Y[(lb+3)*64 + j0 + 12];
        v[0]+=t.x*m0.x; v[1]+=t.x*m0.y; v[2]+=t.x*m0.z; v[3]+=t.x*m0.w;
        v[4]+=t.x*m1.x; v[5]+=t.x*m1.y; v[6]+=t.x*m1.z; v[7]+=t.x*m1.w;
        v[8]+=t.x*m2.x; v[9]+=t.x*m2.y; v[10]+=t.x*m2.z; v[11]+=t.x*m2.w;
        v[12]+=t.x*m3.x; v[13]+=t.x*m3.y; v[14]+=t.x*m3.z; v[15]+=t.x*m3.w;
        v[0]+=t.y*n0.x; v[1]+=t.y*n0.y; v[2]+=t.y*n0.z; v[3]+=t.y*n0.w;
        v[4]+=t.y*n1.x; v[5]+=t.y*n1.y; v[6]+=t.y*n1.z; v[7]+=t.y*n1.w;
        v[8]+=t.y*n2.x; v[9]+=t.y*n2.y; v[10]+=t.y*n2.z; v[11]+=t.y*n2.w;
        v[12]+=t.y*n3.x; v[13]+=t.y*n3.y; v[14]+=t.y*n3.z; v[15]+=t.y*n3.w;
        v[0]+=t.z*p0.x; v[1]+=t.z*p0.y; v[2]+=t.z*p0.z; v[3]+=t.z*p0.w;
        v[4]+=t.z*p1.x; v[5]+=t.z*p1.y; v[6]+=t.z*p1.z; v[7]+=t.z*p1.w;
        v[8]+=t.z*p2.x; v[9]+=t.z*p2.y; v[10]+=t.z*p2.z; v[11]+=t.z*p2.w;
        v[12]+=t.z*p3.x; v[13]+=t.z*p3.y; v[14]+=t.z*p3.z; v[15]+=t.z*p3.w;
        v[0]+=t.w*q0.x; v[1]+=t.w*q0.y; v[2]+=t.w*q0.z; v[3]+=t.w*q0.w;
        v[4]+=t.w*q1.x; v[5]+=t.w*q1.y; v[6]+=t.w*q1.z; v[7]+=t.w*q1.w;
        v[8]+=t.w*q2.x; v[9]+=t.w*q2.y; v[10]+=t.w*q2.z; v[11]+=t.w*q2.w;
        v[12]+=t.w*q3.x; v[13]+=t.w*q3.y; v[14]+=t.w*q3.z; v[15]+=t.w*q3.w;
    }
}

// ---------------- prep (fused): dt, Bbar, expm(A*mean_dt), A_bar^64 ----------------
__global__ void __launch_bounds__(256) prep_kernel(
    const float* __restrict__ A,
    const float* __restrict__ B,
    const float* __restrict__ log_dt)
{
    __shared__ __align__(16) float Mm[4096];
    __shared__ __align__(16) float Tb[4096];
    __shared__ __align__(16) float Rb[4096];
    int tid = threadIdx.x;                 // 256

    // phase 1: dt = exp(log_dt), mean(dt), Bbar = B * dt
    float local = 0.f;
    for (int e = tid; e < HIDDEN; e += 256) {
        float d = expf(log_dt[e]);
        Tb[e] = d;
        local += d;
    }
    Rb[tid] = local;
    __syncthreads();
    for (int s = 128; s > 0; s >>= 1) {
        if (tid < s) Rb[tid] += Rb[tid + s];
        __syncthreads();
    }
    float md = Rb[0] * (1.f / HIDDEN);

    for (int e = tid; e < STATE*HIDDEN; e += 256)
        g_Bbar[e] = B[e] * Tb[e & (HIDDEN - 1)];
    __syncthreads();

    int i  = tid >> 2;
    int j0 = (tid & 3) << 4;

    // phase 2: A_bar = I + M + M^2/2 + ... + M^5/120, M = A*md (||M||~3.4e-3)
    for (int e = tid; e < 4096; e += 256) {
        float m = A[e] * md;
        Mm[e] = m; Tb[e] = m;
        Rb[e] = m + ((e >> 6) == (e & 63) ? 1.f : 0.f);
    }
    __syncthreads();

    for (int k = 2; k <= 5; k++) {
        float v[16];
        mm64(Tb, Mm, i, j0, v);
        float inv = 1.f / (float)k;
        __syncthreads();
        #pragma unroll
        for (int c = 0; c < 16; c++) {
            float nv = v[c] * inv;
            Tb[i*64 + j0 + c] = nv;
            Rb[i*64 + j0 + c] += nv;
        }
        __syncthreads();
    }

    #pragma unroll
    for (int c = 0; c < 16; c++)
        g_AbT[(j0 + c)*64 + i] = Rb[i*64 + j0 + c];   // transposed

    // phase 3: A64 = A_bar^64 via 6 in-place squarings of Rb
    for (int s = 0; s < 6; s++) {
        float v[16];
        mm64(Rb, Rb, i, j0, v);
        __syncthreads();
        #pragma unroll
        for (int c = 0; c < 16; c++) Rb[i*64 + j0 + c] = v[c];
        __syncthreads();
    }
    #pragma unroll
    for (int c = 0; c < 16; c++)
        g_A64T[(j0 + c)*64 + i] = Rb[i*64 + j0 + c];
}

// ---------------- rmsnorm (optionally rounds output to tf32) ----------------
__global__ void rmsnorm_kernel(const float* __restrict__ x,
                               const float* __restrict__ w,
                               float* __restrict__ out, int round_tf32)
{
    int row = blockIdx.x;
    const float4* xr = (const float4*)(x + (size_t)row * HIDDEN);
    float4 v = xr[threadIdx.x];
    float ss = v.x*v.x + v.y*v.y + v.z*v.z + v.w*v.w;
    #pragma unroll
    for (int o = 16; o > 0; o >>= 1) ss += __shfl_down_sync(0xffffffffu, ss, o);
    __shared__ float wr[8];
    __shared__ float sc;
    if ((threadIdx.x & 31) == 0) wr[threadIdx.x >> 5] = ss;
    __syncthreads();
    if (threadIdx.x == 0) {
        float t = 0.f;
        #pragma unroll
        for (int k = 0; k < 8; k++) t += wr[k];
        sc = rsqrtf(t * (1.f / HIDDEN) + 1e-6f);
    }
    __syncthreads();
    float s = sc;
    const float4* ww = (const float4*)w;
    float4 wv = ww[threadIdx.x];
    float4 o4 = make_float4(v.x*s*wv.x, v.y*s*wv.y, v.z*s*wv.z, v.w*s*wv.w);
    if (round_tf32) {
        o4.x = to_tf32(o4.x); o4.y = to_tf32(o4.y);
        o4.z = to_tf32(o4.z); o4.w = to_tf32(o4.w);
    }
    ((float4*)(out + (size_t)row * HIDDEN))[threadIdx.x] = o4;
}

// ---------------- weight rounding to tf32 ----------------
__global__ void round_kernel(const float* __restrict__ in, float* __restrict__ out, int n)
{
    int i = blockIdx.x * 256 + threadIdx.x;
    int stride = gridDim.x * 256;
    for (; i < n; i += stride) out[i] = to_tf32(in[i]);
}

// ---------------- chunked scan ----------------
__global__ void local_scan_kernel()
{
    int c = blockIdx.x, b = blockIdx.y;
    const float* u = g_U + (size_t)(b*SEQ + c*CLEN) * STATE;
    float* sout    = g_S + (size_t)(b*SEQ + c*CLEN) * STATE;

    __shared__ float st[64];
    __shared__ float part[4][64];
    __shared__ float ub[CLEN*64];

    int tid = threadIdx.x;
    int i = tid & 63, p = tid >> 6;

    float a[16];
    #pragma unroll
    for (int jj = 0; jj < 16; jj++) a[jj] = g_AbT[(p*16 + jj)*64 + i];

    for (int e = tid; e < CLEN*64; e += 256) ub[e] = u[e];
    if (tid < 64) st[i] = 0.f;
    __syncthreads();

    for (int t = 0; t < CLEN; t++) {
        float acc = 0.f;
        #pragma unroll
        for (int jj = 0; jj < 16; jj++) acc += a[jj] * st[p*16 + jj];
        part[p][i] = acc;
        __syncthreads();
        if (tid < 64) {
            float v = part[0][i] + part[1][i] + part[2][i] + part[3][i] + ub[t*64 + i];
            st[i] = v;
            sout[(size_t)t*STATE + i] = v;
        }
        __syncthreads();
    }
    if (tid < 64) g_tail[(size_t)(b*NCHUNK + c)*STATE + i] = st[i];
}

__global__ void carry_kernel()
{
    int b = blockIdx.x;
    __shared__ float st[64];
    __shared__ float part[4][64];
    __shared__ float tails[NCHUNK*64];

    int tid = threadIdx.x;
    int i = tid & 63, p = tid >> 6;

    float a[16];
    #pragma unroll
    for (int jj = 0; jj < 16; jj++) a[jj] = g_A64T[(p*16 + jj)*64 + i];

    for (int e = tid; e < NCHUNK*64; e += 256)
        tails[e] = g_tail[(size_t)b*NCHUNK*STATE + e];
    if (tid < 64) {
        st[i] = 0.f;
        g_carry[(size_t)b*NCHUNK*STATE + i] = 0.f;
    }
    __syncthreads();

    for (int c = 1; c < NCHUNK; c++) {
        float acc = 0.f;
        #pragma unroll
        for (int jj = 0; jj < 16; jj++) acc += a[jj] * st[p*16 + jj];
        part[p][i] = acc;
        __syncthreads();
        if (tid < 64) {
            float v = part[0][i] + part[1][i] + part[2][i] + part[3][i]
                    + tails[(c-1)*64 + i];
            st[i] = v;
            g_carry[(size_t)(b*NCHUNK + c)*STATE + i] = v;
        }
        __syncthreads();
    }
}

__global__ void fixup_kernel()
{
    int c = blockIdx.x, b = blockIdx.y;
    float* sout = g_S + (size_t)(b*SEQ + c*CLEN) * STATE;

    __shared__ float st[64];
    __shared__ float part[4][64];

    int tid = threadIdx.x;
    int i = tid & 63, p = tid >> 6;

    float a[16];
    #pragma unroll
    for (int jj = 0; jj < 16; jj++) a[jj] = g_AbT[(p*16 + jj)*64 + i];

    if (tid < 64) st[i] = g_carry[(size_t)(b*NCHUNK + c)*STATE + i];
    __syncthreads();

    for (int t = 0; t < CLEN; t++) {
        float acc = 0.f;
        #pragma unroll
        for (int jj = 0; jj < 16; jj++) acc += a[jj] * st[p*16 + jj];
        part[p][i] = acc;
        __syncthreads();
        if (tid < 64) {
            float v = part[0][i] + part[1][i] + part[2][i] + part[3][i];
            st[i] = v;
            sout[(size_t)t*STATE + i] += v;
        }
        __syncthreads();
    }
}

// ---------------- SIMT SGEMM (small GEMMs + mode-1 epilogue) ----------------
#define BM 64
#define BN 128
#define BK 16
__global__ void __launch_bounds__(256) sgemm_kernel(
    const float* __restrict__ A, const float* __restrict__ Bm,
    int M, int N, int K, float* __restrict__ out, int mode,
    const float* __restrict__ res, const float* __restrict__ extra,
    const float* __restrict__ dvec)
{
    __shared__ float As[BK][BM];
    __shared__ float Bs[BK][BN];
    int tid = threadIdx.x;
    int m0 = blockIdx.y * BM, n0 = blockIdx.x * BN;

    int lr = tid >> 2;
    int lk = (tid & 3) * 4;
    const float* Ap  = A  + (size_t)(m0 + lr) * K + lk;
    int bn1 = n0 + lr, bn2 = n0 + lr + 64;
    const float* Bp1 = Bm + (size_t)bn1 * K + lk;
    const float* Bp2 = Bm + (size_t)bn2 * K + lk;
    bool v1 = bn1 < N, v2 = bn2 < N;

    int wid = tid >> 5, lane = tid & 31;
    float acc[8][4];
    #pragma unroll
    for (int r = 0; r < 8; r++)
        #pragma unroll
        for (int c = 0; c < 4; c++) acc[r][c] = 0.f;

    const float4 z4 = make_float4(0.f, 0.f, 0.f, 0.f);
    for (int k0 = 0; k0 < K; k0 += BK) {
        float4 av = *(const float4*)(Ap + k0);
        float4 b1 = v1 ? *(const float4*)(Bp1 + k0) : z4;
        float4 b2 = v2 ? *(const float4*)(Bp2 + k0) : z4;
        As[lk+0][lr] = av.x; As[lk+1][lr] = av.y; As[lk+2][lr] = av.z; As[lk+3][lr] = av.w;
        Bs[lk+0][lr] = b1.x; Bs[lk+1][lr] = b1.y; Bs[lk+2][lr] = b1.z; Bs[lk+3][lr] = b1.w;
        Bs[lk+0][lr+64] = b2.x; Bs[lk+1][lr+64] = b2.y; Bs[lk+2][lr+64] = b2.z; Bs[lk+3][lr+64] = b2.w;
        __syncthreads();
        #pragma unroll
        for (int kk = 0; kk < BK; kk++) {
            float4 b  = *(const float4*)&Bs[kk][lane*4];
            float4 a0 = *(const float4*)&As[kk][wid*8];
            float4 a1 = *(const float4*)&As[kk][wid*8 + 4];
            float ar[8] = {a0.x,a0.y,a0.z,a0.w,a1.x,a1.y,a1.z,a1.w};
            float br[4] = {b.x,b.y,b.z,b.w};
            #pragma unroll
            for (int r = 0; r < 8; r++)
                #pragma unroll
                for (int c = 0; c < 4; c++)
                    acc[r][c] += ar[r] * br[c];
        }
        __syncthreads();
    }

    #pragma unroll
    for (int r = 0; r < 8; r++) {
        int row = m0 + wid*8 + r;
        #pragma unroll
        for (int c = 0; c < 4; c++) {
            int col = n0 + lane*4 + c;
            if (col < N) {
                size_t idx = (size_t)row * N + col;
                float v = acc[r][c];
                if (mode == 1) v = res[idx] + v + dvec[col]*extra[idx];
                out[idx] = v;
            }
        }
    }
}

// ---------------- tf32 tensor-core GEMM (R2 v1): C = A[M,K] @ B[N,K]^T ----------------
// CTA 128x128x32, 8 warps (2x4), warp tile 64x32, mma.m16n8k8, 2-stage cp.async,
// 64 KB dynamic smem -> 2 CTAs/SM.
__device__ __forceinline__ void cp16(float* s, const float* g) {
    uint32_t sa = (uint32_t)__cvta_generic_to_shared(s);
    asm volatile("cp.async.cg.shared.global [%0], [%1], 16;\n" :: "r"(sa), "l"(g));
}
__device__ __forceinline__ void mma_tf32(float* d,
    uint32_t a0, uint32_t a1, uint32_t a2, uint32_t a3, uint32_t b0, uint32_t b1)
{
    asm volatile(
        "mma.sync.aligned.m16n8k8.row.col.f32.tf32.tf32.f32 "
        "{%0,%1,%2,%3}, {%4,%5,%6,%7}, {%8,%9}, {%0,%1,%2,%3};\n"
        : "+f"(d[0]), "+f"(d[1]), "+f"(d[2]), "+f"(d[3])
        : "r"(a0), "r"(a1), "r"(a2), "r"(a3), "r"(b0), "r"(b1));
}

// modes: 0 plain; 2 out = tf32(silu(res)*acc); 3 out = res + acc
__global__ void __launch_bounds__(256) gemm_tf32(
    const float* __restrict__ A, const float* __restrict__ Bm,
    int M, int N, int K, float* __restrict__ out, int mode,
    const float* __restrict__ res)
{
    extern __shared__ __align__(16) float sm[];  // 2 stages x (A 4096 + B 4096)
    int tid = threadIdx.x;
    int m0 = blockIdx.y * 128, n0 = blockIdx.x * 128;

    int lrow = tid >> 3, k4 = tid & 7;
    const float* Ag = A  + (size_t)(m0 + lrow) * K + k4*4;
    const float* Bg = Bm + (size_t)(n0 + lrow) * K + k4*4;

    int lane = tid & 31, warp = tid >> 5;
    int wm = warp & 1, wn = warp >> 1;     // 2 x 4 warp grid, warp tile 64x32
    int gid = lane >> 2, tig = lane & 3;

    float acc[4][4][4];
    #pragma unroll
    for (int mt = 0; mt < 4; mt++)
        #pragma unroll
        for (int nt = 0; nt < 4; nt++)
            #pragma unroll
            for (int r = 0; r < 4; r++) acc[mt][nt][r] = 0.f;

    int NT = K >> 5;

    #define LOAD_STAGE(kt, s) do {                                            \
        float* As_ = sm + (s)*8192;                                           \
        float* Bs_ = As_ + 4096;                                              \
        int k0_ = (kt) << 5;                                                  \
        _Pragma("unroll")                                                     \
        for (int p_ = 0; p_ < 4; p_++) {                                      \
            int r_ = lrow + p_*32;                                            \
            int slot_ = r_*8 + (k4 ^ (r_ & 7));                               \
            cp16(As_ + slot_*4, Ag + (size_t)p_*32*K + k0_);                  \
            cp16(Bs_ + slot_*4, Bg + (size_t)p_*32*K + k0_);                  \
        }                                                                     \
        asm volatile("cp.async.commit_group;\n");                             \
    } while (0)

    LOAD_STAGE(0, 0);

    for (int kt = 0; kt < NT; kt++) {
        if (kt + 1 < NT) {
            LOAD_STAGE(kt + 1, (kt + 1) & 1);
            asm volatile("cp.async.wait_group 1;\n");
        } else {
            asm volatile("cp.async.wait_group 0;\n");
        }
        __syncthreads();

        const float* As = sm + (kt & 1)*8192;
        const float* Bs = As + 4096;

        #pragma unroll
        for (int ks = 0; ks < 4; ks++) {
            uint32_t bf[4][2];
            #pragma unroll
            for (int nt = 0; nt < 4; nt++) {
                int c = wn*32 + nt*8 + gid;
                bf[nt][0] = __float_as_uint(Bs[c*32 + (((2*ks)   ^ (c & 7)) << 2) + tig]);
                bf[nt][1] = __float_as_uint(Bs[c*32 + (((2*ks+1) ^ (c & 7)) << 2) + tig]);
            }
            #pragma unroll
            for (int mt = 0; mt < 4; mt++) {
                int r = wm*64 + mt*16 + gid;
                int r8 = r + 8;
                uint32_t a0 = __float_as_uint(As[r *32 + (((2*ks)   ^ (r  & 7)) << 2) + tig]);
                uint32_t a1 = __float_as_uint(As[r8*32 + (((2*ks)   ^ (r8 & 7)) << 2) + tig]);
                uint32_t a2 = __float_as_uint(As[r *32 + (((2*ks+1) ^ (r  & 7)) << 2) + tig]);
                uint32_t a3 = __float_as_uint(As[r8*32 + (((2*ks+1) ^ (r8 & 7)) << 2) + tig]);
                #pragma unroll
                for (int nt = 0; nt < 4; nt++)
                    mma_tf32(acc[mt][nt], a0, a1, a2, a3, bf[nt][0], bf[nt][1]);
            }
        }
        __syncthreads();
    }
    #undef LOAD_STAGE

    #pragma unroll
    for (int mt = 0; mt < 4; mt++) {
        #pragma unroll
        for (int nt = 0; nt < 4; nt++) {
            int row0 = m0 + wm*64 + mt*16 + gid;
            int col0 = n0 + wn*32 + nt*8 + tig*2;
            #pragma unroll
            for (int half = 0; half < 2; half++) {
                int row = row0 + half*8;
                size_t idx = (size_t)row * N + col0;
                float v0 = acc[mt][nt][half*2 + 0];
                float v1 = acc[mt][nt][half*2 + 1];
                if (mode == 2) {
                    float2 g2 = *(const float2*)(res + idx);
                    v0 = to_tf32(v0 * (g2.x / (1.f + expf(-g2.x))));
                    v1 = to_tf32(v1 * (g2.y / (1.f + expf(-g2.y))));
                } else if (mode == 3) {
                    float2 r2 = *(const float2*)(res + idx);
                    v0 += r2.x;
                    v1 += r2.y;
                }
                *(float2*)(out + idx) = make_float2(v0, v1);
            }
        }
    }
}

// ---------------- launch ----------------
extern "C" void kernel_launch(void* const* d_in, const int* in_sizes, int n_in,
                              void* d_out, int out_size)
{
    const float* x      = (const float*)d_in[0];
    const float* A      = (const float*)d_in[1];
    const float* B      = (const float*)d_in[2];
    const float* C      = (const float*)d_in[3];
    const float* D      = (const float*)d_in[4];
    const float* log_dt = (const float*)d_in[5];
    const float* w_gate = (const float*)d_in[6];
    const float* w_up   = (const float*)d_in[7];
    const float* w_down = (const float*)d_in[8];
    const float* ln1    = (const float*)d_in[9];
    const float* ln2    = (const float*)d_in[10];
    float* out = (float*)d_out;

    float *hn1, *h, *hn2, *U, *S, *act, *Bbar, *wg, *wu, *wd;
    cudaGetSymbolAddress((void**)&hn1,  g_hn1);
    cudaGetSymbolAddress((void**)&h,    g_h);
    cudaGetSymbolAddress((void**)&hn2,  g_hn2);
    cudaGetSymbolAddress((void**)&U,    g_U);
    cudaGetSymbolAddress((void**)&S,    g_S);
    cudaGetSymbolAddress((void**)&act,  g_act);
    cudaGetSymbolAddress((void**)&Bbar, g_Bbar);
    cudaGetSymbolAddress((void**)&wg,   g_wg);
    cudaGetSymbolAddress((void**)&wu,   g_wu);
    cudaGetSymbolAddress((void**)&wd,   g_wd);

    cudaFuncSetAttribute(gemm_tf32, cudaFuncAttributeMaxDynamicSharedMemorySize, 65536);
    const int DSMEM = 65536;

    // weight rounding (independent of SSM path)
    round_kernel<<<512, 256>>>(w_gate, wg, INTER*HIDDEN);
    round_kernel<<<512, 256>>>(w_up,   wu, INTER*HIDDEN);
    round_kernel<<<512, 256>>>(w_down, wd, HIDDEN*INTER);

    // SSM path
    prep_kernel<<<1, 256>>>(A, B, log_dt);
    rmsnorm_kernel<<<ROWS, 256>>>(x, ln1, hn1, 0);
    sgemm_kernel<<<dim3(1, ROWS/BM), 256>>>(hn1, Bbar, ROWS, STATE, HIDDEN,
                                            U, 0, nullptr, nullptr, nullptr);
    local_scan_kernel<<<dim3(NCHUNK, BATCH), 256>>>();
    carry_kernel<<<BATCH, 256>>>();
    fixup_kernel<<<dim3(NCHUNK, BATCH), 256>>>();
    // h = x + S @ C^T + D*hn1
    sgemm_kernel<<<dim3(HIDDEN/BN, ROWS/BM), 256>>>(S, C, ROWS, HIDDEN, STATE,
                                                    h, 1, x, hn1, D);
    // FFN (tf32 tensor cores)
    rmsnorm_kernel<<<ROWS, 256>>>(h, ln2, hn2, 1);
    gemm_tf32<<<dim3(INTER/128, ROWS/128), 256, DSMEM>>>(hn2, wg, ROWS, INTER, HIDDEN,
                                                         act, 0, nullptr);
    gemm_tf32<<<dim3(INTER/128, ROWS/128), 256, DSMEM>>>(hn2, wu, ROWS, INTER, HIDDEN,
                                                         act, 2, act);
    gemm_tf32<<<dim3(HIDDEN/128, ROWS/128), 256, DSMEM>>>(act, wd, ROWS, HIDDEN, INTER,
                                                          out, 3, h);
}

// round 5
// speedup vs baseline: 1.3741x; 1.2385x over previous
#include <cuda_runtime.h>
#include <cuda_fp16.h>
#include <math.h>
#include <stdint.h>

#define HIDDEN 1024
#define STATE  64
#define INTER  4096
#define BATCH  4
#define SEQ    2048
#define ROWS   (BATCH*SEQ)   // 8192
#define NCHUNK 32
#define CLEN   64            // NCHUNK*CLEN == SEQ

// ---------------- scratch (static device allocations; no cudaMalloc) ----------------
__device__ float  g_hn1[ROWS*HIDDEN];
__device__ float  g_h  [ROWS*HIDDEN];
__device__ __half g_hn2h[ROWS*HIDDEN];
__device__ float  g_U  [ROWS*STATE];
__device__ float  g_S  [ROWS*STATE];
__device__ float  g_gate[ROWS*INTER];     // gate pre-activation (fp32)
__device__ __half g_acth[ROWS*INTER];     // silu(gate)*up (half)
__device__ float  g_Bbar[STATE*HIDDEN];
__device__ float  g_AbT [STATE*STATE];    // AbT[j*64+i] = A_bar[i][j]
__device__ float  g_A64T[STATE*STATE];
__device__ float  g_tail [BATCH*NCHUNK*STATE];
__device__ float  g_carry[BATCH*NCHUNK*STATE];
__device__ __half g_wgh[INTER*HIDDEN];    // fp16 weights
__device__ __half g_wuh[INTER*HIDDEN];
__device__ __half g_wdh[HIDDEN*INTER];

// 64x64 smem matmul, 4x4 thread tile: thread (ti=tid>>4, tj=tid&15) computes
// rows i0..i0+3 x cols j0..j0+3. Per 4-k block: 8 LDS.128 + 64 FMA.
__device__ __forceinline__ void mm64(const float* __restrict__ X,
                                     const float* __restrict__ Y,
                                     int i0, int j0, float v[16])
{
    #pragma unroll
    for (int c = 0; c < 16; c++) v[c] = 0.f;
    #pragma unroll
    for (int lb = 0; lb < 64; lb += 4) {
        float4 x0 = *(const float4*)&X[(i0+0)*64 + lb];
        float4 x1 = *(const float4*)&X[(i0+1)*64 + lb];
        float4 x2 = *(const float4*)&X[(i0+2)*64 + lb];
        float4 x3 = *(const float4*)&X[(i0+3)*64 + lb];
        float4 y0 = *(const float4*)&Y[(lb+0)*64 + j0];
        float4 y1 = *(const float4*)&Y[(lb+1)*64 + j0];
        float4 y2 = *(const float4*)&Y[(lb+2)*64 + j0];
        float4 y3 = *(const float4*)&Y[(lb+3)*64 + j0];
        v[0] += x0.x*y0.x + x0.y*y1.x + x0.z*y2.x + x0.w*y3.x;
        v[1] += x0.x*y0.y + x0.y*y1.y + x0.z*y2.y + x0.w*y3.y;
        v[2] += x0.x*y0.z + x0.y*y1.z + x0.z*y2.z + x0.w*y3.z;
        v[3] += x0.x*y0.w + x0.y*y1.w + x0.z*y2.w + x0.w*y3.w;
        v[4] += x1.x*y0.x + x1.y*y1.x + x1.z*y2.x + x1.w*y3.x;
        v[5] += x1.x*y0.y + x1.y*y1.y + x1.z*y2.y + x1.w*y3.y;
        v[6] += x1.x*y0.z + x1.y*y1.z + x1.z*y2.z + x1.w*y3.z;
        v[7] += x1.x*y0.w + x1.y*y1.w + x1.z*y2.w + x1.w*y3.w;
        v[8] += x2.x*y0.x + x2.y*y1.x + x2.z*y2.x + x2.w*y3.x;
        v[9] += x2.x*y0.y + x2.y*y1.y + x2.z*y2.y + x2.w*y3.y;
        v[10]+= x2.x*y0.z + x2.y*y1.z + x2.z*y2.z + x2.w*y3.z;
        v[11]+= x2.x*y0.w + x2.y*y1.w + x2.z*y2.w + x2.w*y3.w;
        v[12]+= x3.x*y0.x + x3.y*y1.x + x3.z*y2.x + x3.w*y3.x;
        v[13]+= x3.x*y0.y + x3.y*y1.y + x3.z*y2.y + x3.w*y3.y;
        v[14]+= x3.x*y0.z + x3.y*y1.z + x3.z*y2.z + x3.w*y3.z;
        v[15]+= x3.x*y0.w + x3.y*y1.w + x3.z*y2.w + x3.w*y3.w;
    }
}

// ---------------- prep (fused): dt, Bbar, expm(A*mean_dt), A_bar^64 ----------------
__global__ void __launch_bounds__(256) prep_kernel(
    const float* __restrict__ A,
    const float* __restrict__ B,
    const float* __restrict__ log_dt)
{
    __shared__ __align__(16) float Mm[4096];
    __shared__ __align__(16) float Tb[4096];
    __shared__ __align__(16) float Rb[4096];
    int tid = threadIdx.x;                 // 256

    // phase 1: dt = exp(log_dt), mean(dt), Bbar = B * dt
    float local = 0.f;
    for (int e = tid; e < HIDDEN; e += 256) {
        float d = expf(log_dt[e]);
        Tb[e] = d;
        local += d;
    }
    Rb[tid] = local;
    __syncthreads();
    for (int s = 128; s > 0; s >>= 1) {
        if (tid < s) Rb[tid] += Rb[tid + s];
        __syncthreads();
    }
    float md = Rb[0] * (1.f / HIDDEN);

    for (int e = tid; e < STATE*HIDDEN; e += 256)
        g_Bbar[e] = B[e] * Tb[e & (HIDDEN - 1)];
    __syncthreads();

    int i0 = (tid >> 4) * 4;
    int j0 = (tid & 15) * 4;

    // phase 2: A_bar = I + M + ... + M^5/120, M = A*md (||M|| ~ 3.4e-3 -> exact)
    for (int e = tid; e < 4096; e += 256) {
        float m = A[e] * md;
        Mm[e] = m; Tb[e] = m;
        Rb[e] = m + ((e >> 6) == (e & 63) ? 1.f : 0.f);
    }
    __syncthreads();

    for (int k = 2; k <= 5; k++) {
        float v[16];
        mm64(Tb, Mm, i0, j0, v);
        float inv = 1.f / (float)k;
        __syncthreads();
        #pragma unroll
        for (int r = 0; r < 4; r++)
            #pragma unroll
            for (int c = 0; c < 4; c++) {
                float nv = v[r*4 + c] * inv;
                Tb[(i0+r)*64 + j0 + c] = nv;
                Rb[(i0+r)*64 + j0 + c] += nv;
            }
        __syncthreads();
    }

    #pragma unroll
    for (int r = 0; r < 4; r++)
        #pragma unroll
        for (int c = 0; c < 4; c++)
            g_AbT[(j0+c)*64 + (i0+r)] = Rb[(i0+r)*64 + j0 + c];   // transposed

    // phase 3: A64 = A_bar^64 via 6 in-place squarings
    for (int s = 0; s < 6; s++) {
        float v[16];
        mm64(Rb, Rb, i0, j0, v);
        __syncthreads();
        #pragma unroll
        for (int r = 0; r < 4; r++)
            #pragma unroll
            for (int c = 0; c < 4; c++)
                Rb[(i0+r)*64 + j0 + c] = v[r*4 + c];
        __syncthreads();
    }
    #pragma unroll
    for (int r = 0; r < 4; r++)
        #pragma unroll
        for (int c = 0; c < 4; c++)
            g_A64T[(j0+c)*64 + (i0+r)] = Rb[(i0+r)*64 + j0 + c];
}

// ---------------- rmsnorm -> fp32 ----------------
__global__ void rmsnorm_kernel(const float* __restrict__ x,
                               const float* __restrict__ w,
                               float* __restrict__ out)
{
    int row = blockIdx.x;
    const float4* xr = (const float4*)(x + (size_t)row * HIDDEN);
    float4 v = xr[threadIdx.x];
    float ss = v.x*v.x + v.y*v.y + v.z*v.z + v.w*v.w;
    #pragma unroll
    for (int o = 16; o > 0; o >>= 1) ss += __shfl_down_sync(0xffffffffu, ss, o);
    __shared__ float wr[8];
    __shared__ float sc;
    if ((threadIdx.x & 31) == 0) wr[threadIdx.x >> 5] = ss;
    __syncthreads();
    if (threadIdx.x == 0) {
        float t = 0.f;
        #pragma unroll
        for (int k = 0; k < 8; k++) t += wr[k];
        sc = rsqrtf(t * (1.f / HIDDEN) + 1e-6f);
    }
    __syncthreads();
    float s = sc;
    float4 wv = ((const float4*)w)[threadIdx.x];
    float4 o4 = make_float4(v.x*s*wv.x, v.y*s*wv.y, v.z*s*wv.z, v.w*s*wv.w);
    ((float4*)(out + (size_t)row * HIDDEN))[threadIdx.x] = o4;
}

// ---------------- rmsnorm -> fp16 ----------------
__global__ void rmsnorm_h_kernel(const float* __restrict__ x,
                                 const float* __restrict__ w,
                                 __half* __restrict__ out)
{
    int row = blockIdx.x;
    const float4* xr = (const float4*)(x + (size_t)row * HIDDEN);
    float4 v = xr[threadIdx.x];
    float ss = v.x*v.x + v.y*v.y + v.z*v.z + v.w*v.w;
    #pragma unroll
    for (int o = 16; o > 0; o >>= 1) ss += __shfl_down_sync(0xffffffffu, ss, o);
    __shared__ float wr[8];
    __shared__ float sc;
    if ((threadIdx.x & 31) == 0) wr[threadIdx.x >> 5] = ss;
    __syncthreads();
    if (threadIdx.x == 0) {
        float t = 0.f;
        #pragma unroll
        for (int k = 0; k < 8; k++) t += wr[k];
        sc = rsqrtf(t * (1.f / HIDDEN) + 1e-6f);
    }
    __syncthreads();
    float s = sc;
    float4 wv = ((const float4*)w)[threadIdx.x];
    __half2 h0 = __floats2half2_rn(v.x*s*wv.x, v.y*s*wv.y);
    __half2 h1 = __floats2half2_rn(v.z*s*wv.z, v.w*s*wv.w);
    __half2* op = (__half2*)(out + (size_t)row * HIDDEN) + threadIdx.x*2;
    op[0] = h0; op[1] = h1;
}

// ---------------- fp32 -> fp16 weight conversion ----------------
__global__ void f2h_kernel(const float* __restrict__ in, __half* __restrict__ out, int n2)
{
    int i = blockIdx.x * 256 + threadIdx.x;
    int stride = gridDim.x * 256;
    const float2* in2 = (const float2*)in;
    __half2* out2 = (__half2*)out;
    for (; i < n2; i += stride) {
        float2 v = in2[i];
        out2[i] = __floats2half2_rn(v.x, v.y);
    }
}

// ---------------- chunked scan ----------------
__global__ void local_scan_kernel()
{
    int c = blockIdx.x, b = blockIdx.y;
    const float* u = g_U + (size_t)(b*SEQ + c*CLEN) * STATE;
    float* sout    = g_S + (size_t)(b*SEQ + c*CLEN) * STATE;

    __shared__ float st[64];
    __shared__ float part[4][64];
    __shared__ float ub[CLEN*64];

    int tid = threadIdx.x;
    int i = tid & 63, p = tid >> 6;

    float a[16];
    #pragma unroll
    for (int jj = 0; jj < 16; jj++) a[jj] = g_AbT[(p*16 + jj)*64 + i];

    for (int e = tid; e < CLEN*64; e += 256) ub[e] = u[e];
    if (tid < 64) st[i] = 0.f;
    __syncthreads();

    for (int t = 0; t < CLEN; t++) {
        float acc = 0.f;
        #pragma unroll
        for (int jj = 0; jj < 16; jj++) acc += a[jj] * st[p*16 + jj];
        part[p][i] = acc;
        __syncthreads();
        if (tid < 64) {
            float v = part[0][i] + part[1][i] + part[2][i] + part[3][i] + ub[t*64 + i];
            st[i] = v;
            sout[(size_t)t*STATE + i] = v;
        }
        __syncthreads();
    }
    if (tid < 64) g_tail[(size_t)(b*NCHUNK + c)*STATE + i] = st[i];
}

__global__ void carry_kernel()
{
    int b = blockIdx.x;
    __shared__ float st[64];
    __shared__ float part[4][64];
    __shared__ float tails[NCHUNK*64];

    int tid = threadIdx.x;
    int i = tid & 63, p = tid >> 6;

    float a[16];
    #pragma unroll
    for (int jj = 0; jj < 16; jj++) a[jj] = g_A64T[(p*16 + jj)*64 + i];

    for (int e = tid; e < NCHUNK*64; e += 256)
        tails[e] = g_tail[(size_t)b*NCHUNK*STATE + e];
    if (tid < 64) {
        st[i] = 0.f;
        g_carry[(size_t)b*NCHUNK*STATE + i] = 0.f;
    }
    __syncthreads();

    for (int c = 1; c < NCHUNK; c++) {
        float acc = 0.f;
        #pragma unroll
        for (int jj = 0; jj < 16; jj++) acc += a[jj] * st[p*16 + jj];
        part[p][i] = acc;
        __syncthreads();
        if (tid < 64) {
            float v = part[0][i] + part[1][i] + part[2][i] + part[3][i]
                    + tails[(c-1)*64 + i];
            st[i] = v;
            g_carry[(size_t)(b*NCHUNK + c)*STATE + i] = v;
        }
        __syncthreads();
    }
}

__global__ void fixup_kernel()
{
    int c = blockIdx.x, b = blockIdx.y;
    float* sout = g_S + (size_t)(b*SEQ + c*CLEN) * STATE;

    __shared__ float st[64];
    __shared__ float part[4][64];

    int tid = threadIdx.x;
    int i = tid & 63, p = tid >> 6;

    float a[16];
    #pragma unroll
    for (int jj = 0; jj < 16; jj++) a[jj] = g_AbT[(p*16 + jj)*64 + i];

    if (tid < 64) st[i] = g_carry[(size_t)(b*NCHUNK + c)*STATE + i];
    __syncthreads();

    for (int t = 0; t < CLEN; t++) {
        float acc = 0.f;
        #pragma unroll
        for (int jj = 0; jj < 16; jj++) acc += a[jj] * st[p*16 + jj];
        part[p][i] = acc;
        __syncthreads();
        if (tid < 64) {
            float v = part[0][i] + part[1][i] + part[2][i] + part[3][i];
            st[i] = v;
            sout[(size_t)t*STATE + i] += v;
        }
        __syncthreads();
    }
}

// ---------------- SIMT SGEMM (small GEMMs + mode-1 epilogue) ----------------
#define BM 64
#define BN 128
#define BK 16
__global__ void __launch_bounds__(256) sgemm_kernel(
    const float* __restrict__ A, const float* __restrict__ Bm,
    int M, int N, int K, float* __restrict__ out, int mode,
    const float* __restrict__ res, const float* __restrict__ extra,
    const float* __restrict__ dvec)
{
    __shared__ float As[BK][BM];
    __shared__ float Bs[BK][BN];
    int tid = threadIdx.x;
    int m0 = blockIdx.y * BM, n0 = blockIdx.x * BN;

    int lr = tid >> 2;
    int lk = (tid & 3) * 4;
    const float* Ap  = A  + (size_t)(m0 + lr) * K + lk;
    int bn1 = n0 + lr, bn2 = n0 + lr + 64;
    const float* Bp1 = Bm + (size_t)bn1 * K + lk;
    const float* Bp2 = Bm + (size_t)bn2 * K + lk;
    bool v1 = bn1 < N, v2 = bn2 < N;

    int wid = tid >> 5, lane = tid & 31;
    float acc[8][4];
    #pragma unroll
    for (int r = 0; r < 8; r++)
        #pragma unroll
        for (int c = 0; c < 4; c++) acc[r][c] = 0.f;

    const float4 z4 = make_float4(0.f, 0.f, 0.f, 0.f);
    for (int k0 = 0; k0 < K; k0 += BK) {
        float4 av = *(const float4*)(Ap + k0);
        float4 b1 = v1 ? *(const float4*)(Bp1 + k0) : z4;
        float4 b2 = v2 ? *(const float4*)(Bp2 + k0) : z4;
        As[lk+0][lr] = av.x; As[lk+1][lr] = av.y; As[lk+2][lr] = av.z; As[lk+3][lr] = av.w;
        Bs[lk+0][lr] = b1.x; Bs[lk+1][lr] = b1.y; Bs[lk+2][lr] = b1.z; Bs[lk+3][lr] = b1.w;
        Bs[lk+0][lr+64] = b2.x; Bs[lk+1][lr+64] = b2.y; Bs[lk+2][lr+64] = b2.z; Bs[lk+3][lr+64] = b2.w;
        __syncthreads();
        #pragma unroll
        for (int kk = 0; kk < BK; kk++) {
            float4 b  = *(const float4*)&Bs[kk][lane*4];
            float4 a0 = *(const float4*)&As[kk][wid*8];
            float4 a1 = *(const float4*)&As[kk][wid*8 + 4];
            float ar[8] = {a0.x,a0.y,a0.z,a0.w,a1.x,a1.y,a1.z,a1.w};
            float br[4] = {b.x,b.y,b.z,b.w};
            #pragma unroll
            for (int r = 0; r < 8; r++)
                #pragma unroll
                for (int c = 0; c < 4; c++)
                    acc[r][c] += ar[r] * br[c];
        }
        __syncthreads();
    }

    #pragma unroll
    for (int r = 0; r < 8; r++) {
        int row = m0 + wid*8 + r;
        #pragma unroll
        for (int c = 0; c < 4; c++) {
            int col = n0 + lane*4 + c;
            if (col < N) {
                size_t idx = (size_t)row * N + col;
                float v = acc[r][c];
                if (mode == 1) v = res[idx] + v + dvec[col]*extra[idx];
                out[idx] = v;
            }
        }
    }
}

// ---------------- fp16 tensor-core GEMM: C = A[M,K] @ B[N,K]^T ----------------
// CTA 128x128x32, 8 warps (2x4), warp tile 64x32, mma.m16n8k16, ldmatrix frags,
// 80B smem row pitch (conflict-free without swizzle), 2-stage cp.async (40KB).
__device__ __forceinline__ void ldsm4(uint32_t& r0, uint32_t& r1,
                                      uint32_t& r2, uint32_t& r3, uint32_t addr)
{
    asm volatile("ldmatrix.sync.aligned.m8n8.x4.shared.b16 {%0,%1,%2,%3}, [%4];"
                 : "=r"(r0), "=r"(r1), "=r"(r2), "=r"(r3) : "r"(addr));
}
__device__ __forceinline__ void cp16s(uint32_t saddr, const void* g)
{
    asm volatile("cp.async.cg.shared.global [%0], [%1], 16;" :: "r"(saddr), "l"(g));
}
__device__ __forceinline__ void mma_f16(float* d, const uint32_t a[4],
                                        uint32_t b0, uint32_t b1)
{
    asm volatile(
        "mma.sync.aligned.m16n8k16.row.col.f32.f16.f16.f32 "
        "{%0,%1,%2,%3}, {%4,%5,%6,%7}, {%8,%9}, {%0,%1,%2,%3};\n"
        : "+f"(d[0]), "+f"(d[1]), "+f"(d[2]), "+f"(d[3])
        : "r"(a[0]), "r"(a[1]), "r"(a[2]), "r"(a[3]), "r"(b0), "r"(b1));
}

#define STAGE_B 20480        // bytes per stage (A 10240 + B 10240), row pitch 80B

// modes: 0 outf=acc; 2 outh = half(silu(res)*acc); 3 outf = res + acc
__global__ void __launch_bounds__(256) gemm_f16(
    const __half* __restrict__ A, const __half* __restrict__ Bm,
    int M, int N, int K, float* __restrict__ outf, __half* __restrict__ outh,
    int mode, const float* __restrict__ res)
{
    extern __shared__ __align__(16) char smem[];
    uint32_t smBase = (uint32_t)__cvta_generic_to_shared(smem);
    int tid = threadIdx.x;
    int m0 = blockIdx.y * 128, n0 = blockIdx.x * 128;

    // loader: thread -> row (tid>>1), 2 chunks of 16B at cpair*16
    int lr = tid >> 1, lc = (tid & 1) * 2;
    const __half* Ag = A  + (size_t)(m0 + lr) * K + lc*8;
    const __half* Bg = Bm + (size_t)(n0 + lr) * K + lc*8;
    uint32_t aDst = smBase + lr*80 + lc*16;
    uint32_t bDst = smBase + 10240 + lr*80 + lc*16;

    int lane = tid & 31, warp = tid >> 5;
    int wm = warp & 1, wn = warp >> 1;     // 2x4 warp grid, warp tile 64x32
    int gid = lane >> 2, tig = lane & 3;

    // ldmatrix per-lane base addresses
    uint32_t aFrag = smBase
        + (uint32_t)(wm*64 + (lane & 7) + ((lane >> 3) & 1)*8) * 80
        + ((lane >> 4) & 1) * 16;
    uint32_t bFrag = smBase + 10240
        + (uint32_t)(wn*32 + ((lane >> 4) & 1)*8 + (lane & 7)) * 80
        + ((lane >> 3) & 1) * 16;

    float acc[4][4][4];
    #pragma unroll
    for (int mt = 0; mt < 4; mt++)
        #pragma unroll
        for (int nt = 0; nt < 4; nt++)
            #pragma unroll
            for (int r = 0; r < 4; r++) acc[mt][nt][r] = 0.f;

    int NT = K >> 5;

    #define LOAD_STAGE(kt, s) do {                                           \
        uint32_t off_ = (uint32_t)(s) * STAGE_B;                             \
        const __half* ga_ = Ag + (size_t)(kt)*32;                            \
        const __half* gb_ = Bg + (size_t)(kt)*32;                            \
        cp16s(aDst + off_,      ga_);                                        \
        cp16s(aDst + off_ + 16, ga_ + 8);                                    \
        cp16s(bDst + off_,      gb_);                                        \
        cp16s(bDst + off_ + 16, gb_ + 8);                                    \
        asm volatile("cp.async.commit_group;\n");                            \
    } while (0)

    LOAD_STAGE(0, 0);

    for (int kt = 0; kt < NT; kt++) {
        if (kt + 1 < NT) {
            LOAD_STAGE(kt + 1, (kt + 1) & 1);
            asm volatile("cp.async.wait_group 1;\n");
        } else {
            asm volatile("cp.async.wait_group 0;\n");
        }
        __syncthreads();

        uint32_t soff = (uint32_t)(kt & 1) * STAGE_B;

        #pragma unroll
        for (int ks = 0; ks < 2; ks++) {
            uint32_t bb[2][4];
            #pragma unroll
            for (int p = 0; p < 2; p++)
                ldsm4(bb[p][0], bb[p][1], bb[p][2], bb[p][3],
                      bFrag + soff + (uint32_t)p*16*80 + ks*32);
            #pragma unroll
            for (int mt = 0; mt < 4; mt++) {
                uint32_t aa[4];
                ldsm4(aa[0], aa[1], aa[2], aa[3],
                      aFrag + soff + (uint32_t)mt*16*80 + ks*32);
                mma_f16(acc[mt][0], aa, bb[0][0], bb[0][1]);
                mma_f16(acc[mt][1], aa, bb[0][2], bb[0][3]);
                mma_f16(acc[mt][2], aa, bb[1][0], bb[1][1]);
                mma_f16(acc[mt][3], aa, bb[1][2], bb[1][3]);
            }
        }
        __syncthreads();
    }
    #undef LOAD_STAGE

    // epilogue: thread (g,t): d0,d1 = row g cols 2t,2t+1; d2,d3 = row g+8
    #pragma unroll
    for (int mt = 0; mt < 4; mt++) {
        #pragma unroll
        for (int nt = 0; nt < 4; nt++) {
            int row0 = m0 + wm*64 + mt*16 + gid;
            int col0 = n0 + wn*32 + nt*8 + tig*2;
            #pragma unroll
            for (int half = 0; half < 2; half++) {
                int row = row0 + half*8;
                size_t idx = (size_t)row * N + col0;
                float v0 = acc[mt][nt][half*2 + 0];
                float v1 = acc[mt][nt][half*2 + 1];
                if (mode == 2) {
                    float2 g2 = *(const float2*)(res + idx);
                    v0 = v0 * (g2.x / (1.f + expf(-g2.x)));
                    v1 = v1 * (g2.y / (1.f + expf(-g2.y)));
                    *(__half2*)(outh + idx) = __floats2half2_rn(v0, v1);
                } else if (mode == 3) {
                    float2 r2 = *(const float2*)(res + idx);
                    *(float2*)(outf + idx) = make_float2(v0 + r2.x, v1 + r2.y);
                } else {
                    *(float2*)(outf + idx) = make_float2(v0, v1);
                }
            }
        }
    }
}

// ---------------- launch ----------------
extern "C" void kernel_launch(void* const* d_in, const int* in_sizes, int n_in,
                              void* d_out, int out_size)
{
    const float* x      = (const float*)d_in[0];
    const float* A      = (const float*)d_in[1];
    const float* B      = (const float*)d_in[2];
    const float* C      = (const float*)d_in[3];
    const float* D      = (const float*)d_in[4];
    const float* log_dt = (const float*)d_in[5];
    const float* w_gate = (const float*)d_in[6];
    const float* w_up   = (const float*)d_in[7];
    const float* w_down = (const float*)d_in[8];
    const float* ln1    = (const float*)d_in[9];
    const float* ln2    = (const float*)d_in[10];
    float* out = (float*)d_out;

    float *hn1, *h, *U, *S, *gate, *Bbar;
    __half *hn2h, *acth, *wgh, *wuh, *wdh;
    cudaGetSymbolAddress((void**)&hn1,  g_hn1);
    cudaGetSymbolAddress((void**)&h,    g_h);
    cudaGetSymbolAddress((void**)&hn2h, g_hn2h);
    cudaGetSymbolAddress((void**)&U,    g_U);
    cudaGetSymbolAddress((void**)&S,    g_S);
    cudaGetSymbolAddress((void**)&gate, g_gate);
    cudaGetSymbolAddress((void**)&acth, g_acth);
    cudaGetSymbolAddress((void**)&Bbar, g_Bbar);
    cudaGetSymbolAddress((void**)&wgh,  g_wgh);
    cudaGetSymbolAddress((void**)&wuh,  g_wuh);
    cudaGetSymbolAddress((void**)&wdh,  g_wdh);

    cudaFuncSetAttribute(gemm_f16, cudaFuncAttributeMaxDynamicSharedMemorySize, 2*STAGE_B);
    const int DSMEM = 2*STAGE_B;   // 40960

    // weight conversion (independent of SSM path)
    f2h_kernel<<<1024, 256>>>(w_gate, wgh, INTER*HIDDEN/2);
    f2h_kernel<<<1024, 256>>>(w_up,   wuh, INTER*HIDDEN/2);
    f2h_kernel<<<1024, 256>>>(w_down, wdh, HIDDEN*INTER/2);

    // SSM path
    prep_kernel<<<1, 256>>>(A, B, log_dt);
    rmsnorm_kernel<<<ROWS, 256>>>(x, ln1, hn1);
    sgemm_kernel<<<dim3(1, ROWS/BM), 256>>>(hn1, Bbar, ROWS, STATE, HIDDEN,
                                            U, 0, nullptr, nullptr, nullptr);
    local_scan_kernel<<<dim3(NCHUNK, BATCH), 256>>>();
    carry_kernel<<<BATCH, 256>>>();
    fixup_kernel<<<dim3(NCHUNK, BATCH), 256>>>();
    // h = x + S @ C^T + D*hn1
    sgemm_kernel<<<dim3(HIDDEN/BN, ROWS/BM), 256>>>(S, C, ROWS, HIDDEN, STATE,
                                                    h, 1, x, hn1, D);
    // FFN (fp16 tensor cores)
    rmsnorm_h_kernel<<<ROWS, 256>>>(h, ln2, hn2h);
    gemm_f16<<<dim3(INTER/128, ROWS/128), 256, DSMEM>>>(hn2h, wgh, ROWS, INTER, HIDDEN,
                                                        gate, nullptr, 0, nullptr);
    gemm_f16<<<dim3(INTER/128, ROWS/128), 256, DSMEM>>>(hn2h, wuh, ROWS, INTER, HIDDEN,
                                                        nullptr, acth, 2, gate);
    gemm_f16<<<dim3(HIDDEN/128, ROWS/128), 256, DSMEM>>>(acth, wdh, ROWS, HIDDEN, INTER,
                                                         out, nullptr, 3, h);
}

// round 7
// speedup vs baseline: 1.5655x; 1.1393x over previous
#include <cuda_runtime.h>
#include <cuda_fp16.h>
#include <math.h>
#include <stdint.h>

#define HIDDEN 1024
#define STATE  64
#define INTER  4096
#define BATCH  4
#define SEQ    2048
#define ROWS   (BATCH*SEQ)   // 8192
#define NCHUNK 32
#define CLEN   64            // NCHUNK*CLEN == SEQ

// ---------------- scratch (static device allocations; no cudaMalloc) ----------------
__device__ float  g_hn1[ROWS*HIDDEN];
__device__ __half g_hn1h[ROWS*HIDDEN];
__device__ float  g_h  [ROWS*HIDDEN];
__device__ __half g_hn2h[ROWS*HIDDEN];
__device__ float  g_U  [ROWS*STATE];
__device__ float  g_S  [ROWS*STATE];
__device__ __half g_Sh [ROWS*STATE];
__device__ float  g_gate[ROWS*INTER];     // gate pre-activation (fp32)
__device__ __half g_acth[ROWS*INTER];     // silu(gate)*up (half)
__device__ __half g_Bbarh[128*HIDDEN];    // rows 64..127 stay zero (zero-init)
__device__ __half g_Ch[HIDDEN*STATE];
__device__ float  g_AbT [STATE*STATE];    // AbT[j*64+i] = A_bar[i][j]
__device__ float  g_A64T[STATE*STATE];
__device__ float  g_tail [BATCH*NCHUNK*STATE];
__device__ float  g_carry[BATCH*NCHUNK*STATE];
__device__ __half g_wgh[INTER*HIDDEN];    // fp16 weights
__device__ __half g_wuh[INTER*HIDDEN];
__device__ __half g_wdh[HIDDEN*INTER];

// ================= small-matrix helper =================
__device__ __forceinline__ void mm64(const float* __restrict__ X,
                                     const float* __restrict__ Y,
                                     int i0, int j0, float v[16])
{
    #pragma unroll
    for (int c = 0; c < 16; c++) v[c] = 0.f;
    #pragma unroll
    for (int lb = 0; lb < 64; lb += 4) {
        float4 x0 = *(const float4*)&X[(i0+0)*64 + lb];
        float4 x1 = *(const float4*)&X[(i0+1)*64 + lb];
        float4 x2 = *(const float4*)&X[(i0+2)*64 + lb];
        float4 x3 = *(const float4*)&X[(i0+3)*64 + lb];
        float4 y0 = *(const float4*)&Y[(lb+0)*64 + j0];
        float4 y1 = *(const float4*)&Y[(lb+1)*64 + j0];
        float4 y2 = *(const float4*)&Y[(lb+2)*64 + j0];
        float4 y3 = *(const float4*)&Y[(lb+3)*64 + j0];
        v[0] += x0.x*y0.x + x0.y*y1.x + x0.z*y2.x + x0.w*y3.x;
        v[1] += x0.x*y0.y + x0.y*y1.y + x0.z*y2.y + x0.w*y3.y;
        v[2] += x0.x*y0.z + x0.y*y1.z + x0.z*y2.z + x0.w*y3.z;
        v[3] += x0.x*y0.w + x0.y*y1.w + x0.z*y2.w + x0.w*y3.w;
        v[4] += x1.x*y0.x + x1.y*y1.x + x1.z*y2.x + x1.w*y3.x;
        v[5] += x1.x*y0.y + x1.y*y1.y + x1.z*y2.y + x1.w*y3.y;
        v[6] += x1.x*y0.z + x1.y*y1.z + x1.z*y2.z + x1.w*y3.z;
        v[7] += x1.x*y0.w + x1.y*y1.w + x1.z*y2.w + x1.w*y3.w;
        v[8] += x2.x*y0.x + x2.y*y1.x + x2.z*y2.x + x2.w*y3.x;
        v[9] += x2.x*y0.y + x2.y*y1.y + x2.z*y2.y + x2.w*y3.y;
        v[10]+= x2.x*y0.z + x2.y*y1.z + x2.z*y2.z + x2.w*y3.z;
        v[11]+= x2.x*y0.w + x2.y*y1.w + x2.z*y2.w + x2.w*y3.w;
        v[12]+= x3.x*y0.x + x3.y*y1.x + x3.z*y2.x + x3.w*y3.x;
        v[13]+= x3.x*y0.y + x3.y*y1.y + x3.z*y2.y + x3.w*y3.y;
        v[14]+= x3.x*y0.z + x3.y*y1.z + x3.z*y2.z + x3.w*y3.z;
        v[15]+= x3.x*y0.w + x3.y*y1.w + x3.z*y2.w + x3.w*y3.w;
    }
}

__global__ void __launch_bounds__(256) prep_kernel(
    const float* __restrict__ A,
    const float* __restrict__ B,
    const float* __restrict__ log_dt)
{
    __shared__ __align__(16) float Mm[4096];
    __shared__ __align__(16) float Tb[4096];
    __shared__ __align__(16) float Rb[4096];
    int tid = threadIdx.x;                 // 256

    float local = 0.f;
    for (int e = tid; e < HIDDEN; e += 256) {
        float d = expf(log_dt[e]);
        Tb[e] = d;
        local += d;
    }
    Rb[tid] = local;
    __syncthreads();
    for (int s = 128; s > 0; s >>= 1) {
        if (tid < s) Rb[tid] += Rb[tid + s];
        __syncthreads();
    }
    float md = Rb[0] * (1.f / HIDDEN);

    for (int e = tid; e < STATE*HIDDEN; e += 256)
        g_Bbarh[e] = __float2half(B[e] * Tb[e & (HIDDEN - 1)]);
    __syncthreads();

    int i0 = (tid >> 4) * 4;
    int j0 = (tid & 15) * 4;

    for (int e = tid; e < 4096; e += 256) {
        float m = A[e] * md;
        Mm[e] = m; Tb[e] = m;
        Rb[e] = m + ((e >> 6) == (e & 63) ? 1.f : 0.f);
    }
    __syncthreads();

    for (int k = 2; k <= 5; k++) {
        float v[16];
        mm64(Tb, Mm, i0, j0, v);
        float inv = 1.f / (float)k;
        __syncthreads();
        #pragma unroll
        for (int r = 0; r < 4; r++)
            #pragma unroll
            for (int c = 0; c < 4; c++) {
                float nv = v[r*4 + c] * inv;
                Tb[(i0+r)*64 + j0 + c] = nv;
                Rb[(i0+r)*64 + j0 + c] += nv;
            }
        __syncthreads();
    }

    #pragma unroll
    for (int r = 0; r < 4; r++)
        #pragma unroll
        for (int c = 0; c < 4; c++)
            g_AbT[(j0+c)*64 + (i0+r)] = Rb[(i0+r)*64 + j0 + c];

    for (int s = 0; s < 6; s++) {
        float v[16];
        mm64(Rb, Rb, i0, j0, v);
        __syncthreads();
        #pragma unroll
        for (int r = 0; r < 4; r++)
            #pragma unroll
            for (int c = 0; c < 4; c++)
                Rb[(i0+r)*64 + j0 + c] = v[r*4 + c];
        __syncthreads();
    }
    #pragma unroll
    for (int r = 0; r < 4; r++)
        #pragma unroll
        for (int c = 0; c < 4; c++)
            g_A64T[(j0+c)*64 + (i0+r)] = Rb[(i0+r)*64 + j0 + c];
}

// ---------------- rmsnorm -> fp32 (+ optional fp16 mirror) ----------------
__global__ void rmsnorm_kernel(const float* __restrict__ x,
                               const float* __restrict__ w,
                               float* __restrict__ outf,
                               __half* __restrict__ outh)
{
    int row = blockIdx.x;
    const float4* xr = (const float4*)(x + (size_t)row * HIDDEN);
    float4 v = xr[threadIdx.x];
    float ss = v.x*v.x + v.y*v.y + v.z*v.z + v.w*v.w;
    #pragma unroll
    for (int o = 16; o > 0; o >>= 1) ss += __shfl_down_sync(0xffffffffu, ss, o);
    __shared__ float wr[8];
    __shared__ float sc;
    if ((threadIdx.x & 31) == 0) wr[threadIdx.x >> 5] = ss;
    __syncthreads();
    if (threadIdx.x == 0) {
        float t = 0.f;
        #pragma unroll
        for (int k = 0; k < 8; k++) t += wr[k];
        sc = rsqrtf(t * (1.f / HIDDEN) + 1e-6f);
    }
    __syncthreads();
    float s = sc;
    float4 wv = ((const float4*)w)[threadIdx.x];
    float4 o4 = make_float4(v.x*s*wv.x, v.y*s*wv.y, v.z*s*wv.z, v.w*s*wv.w);
    if (outf) ((float4*)(outf + (size_t)row * HIDDEN))[threadIdx.x] = o4;
    if (outh) {
        __half2* op = (__half2*)(outh + (size_t)row * HIDDEN) + threadIdx.x*2;
        op[0] = __floats2half2_rn(o4.x, o4.y);
        op[1] = __floats2half2_rn(o4.z, o4.w);
    }
}

// ---------------- fp32 -> fp16 conversion ----------------
__global__ void f2h_kernel(const float* __restrict__ in, __half* __restrict__ out, int n2)
{
    int i = blockIdx.x * 256 + threadIdx.x;
    int stride = gridDim.x * 256;
    const float2* in2 = (const float2*)in;
    __half2* out2 = (__half2*)out;
    for (; i < n2; i += stride) {
        float2 v = in2[i];
        out2[i] = __floats2half2_rn(v.x, v.y);
    }
}

// ---------------- chunked scan ----------------
__global__ void local_scan_kernel()
{
    int c = blockIdx.x, b = blockIdx.y;
    const float* u = g_U + (size_t)(b*SEQ + c*CLEN) * STATE;
    float* sout    = g_S + (size_t)(b*SEQ + c*CLEN) * STATE;

    __shared__ float st[64];
    __shared__ float part[4][64];
    __shared__ float ub[CLEN*64];

    int tid = threadIdx.x;
    int i = tid & 63, p = tid >> 6;

    float a[16];
    #pragma unroll
    for (int jj = 0; jj < 16; jj++) a[jj] = g_AbT[(p*16 + jj)*64 + i];

    for (int e = tid; e < CLEN*64; e += 256) ub[e] = u[e];
    if (tid < 64) st[i] = 0.f;
    __syncthreads();

    for (int t = 0; t < CLEN; t++) {
        float acc = 0.f;
        #pragma unroll
        for (int jj = 0; jj < 16; jj++) acc += a[jj] * st[p*16 + jj];
        part[p][i] = acc;
        __syncthreads();
        if (tid < 64) {
            float v = part[0][i] + part[1][i] + part[2][i] + part[3][i] + ub[t*64 + i];
            st[i] = v;
            sout[(size_t)t*STATE + i] = v;
        }
        __syncthreads();
    }
    if (tid < 64) g_tail[(size_t)(b*NCHUNK + c)*STATE + i] = st[i];
}

__global__ void carry_kernel()
{
    int b = blockIdx.x;
    __shared__ float st[64];
    __shared__ float part[4][64];
    __shared__ float tails[NCHUNK*64];

    int tid = threadIdx.x;
    int i = tid & 63, p = tid >> 6;

    float a[16];
    #pragma unroll
    for (int jj = 0; jj < 16; jj++) a[jj] = g_A64T[(p*16 + jj)*64 + i];

    for (int e = tid; e < NCHUNK*64; e += 256)
        tails[e] = g_tail[(size_t)b*NCHUNK*STATE + e];
    if (tid < 64) {
        st[i] = 0.f;
        g_carry[(size_t)b*NCHUNK*STATE + i] = 0.f;
    }
    __syncthreads();

    for (int c = 1; c < NCHUNK; c++) {
        float acc = 0.f;
        #pragma unroll
        for (int jj = 0; jj < 16; jj++) acc += a[jj] * st[p*16 + jj];
        part[p][i] = acc;
        __syncthreads();
        if (tid < 64) {
            float v = part[0][i] + part[1][i] + part[2][i] + part[3][i]
                    + tails[(c-1)*64 + i];
            st[i] = v;
            g_carry[(size_t)(b*NCHUNK + c)*STATE + i] = v;
        }
        __syncthreads();
    }
}

// fixup: S_final = S_local + A^{t+1} carry; writes HALF S for the tensor GEMM
__global__ void fixup_kernel()
{
    int c = blockIdx.x, b = blockIdx.y;
    const float* sin = g_S  + (size_t)(b*SEQ + c*CLEN) * STATE;
    __half* sout     = g_Sh + (size_t)(b*SEQ + c*CLEN) * STATE;

    __shared__ float st[64];
    __shared__ float part[4][64];

    int tid = threadIdx.x;
    int i = tid & 63, p = tid >> 6;

    float a[16];
    #pragma unroll
    for (int jj = 0; jj < 16; jj++) a[jj] = g_AbT[(p*16 + jj)*64 + i];

    if (tid < 64) st[i] = g_carry[(size_t)(b*NCHUNK + c)*STATE + i];
    __syncthreads();

    for (int t = 0; t < CLEN; t++) {
        float acc = 0.f;
        #pragma unroll
        for (int jj = 0; jj < 16; jj++) acc += a[jj] * st[p*16 + jj];
        part[p][i] = acc;
        __syncthreads();
        if (tid < 64) {
            float v = part[0][i] + part[1][i] + part[2][i] + part[3][i];
            st[i] = v;
            sout[(size_t)t*STATE + i] = __float2half(v + sin[(size_t)t*STATE + i]);
        }
        __syncthreads();
    }
}

// ================= fp16 tensor-core GEMM v3: C = A[M,K] @ B[N,K]^T =================
// CTA 128x128x32, 8 warps (2x4), warp tile 64x32, mma.m16n8k16, ldmatrix frags,
// 80B smem row pitch, 3-stage cp.async, ONE __syncthreads per ktile.
__device__ __forceinline__ void ldsm4(uint32_t& r0, uint32_t& r1,
                                      uint32_t& r2, uint32_t& r3, uint32_t addr)
{
    asm volatile("ldmatrix.sync.aligned.m8n8.x4.shared.b16 {%0,%1,%2,%3}, [%4];"
                 : "=r"(r0), "=r"(r1), "=r"(r2), "=r"(r3) : "r"(addr));
}
__device__ __forceinline__ void cp16s(uint32_t saddr, const void* g)
{
    asm volatile("cp.async.cg.shared.global [%0], [%1], 16;" :: "r"(saddr), "l"(g));
}
__device__ __forceinline__ void mma_f16(float* d, const uint32_t a[4],
                                        uint32_t b0, uint32_t b1)
{
    asm volatile(
        "mma.sync.aligned.m16n8k16.row.col.f32.f16.f16.f32 "
        "{%0,%1,%2,%3}, {%4,%5,%6,%7}, {%8,%9}, {%0,%1,%2,%3};\n"
        : "+f"(d[0]), "+f"(d[1]), "+f"(d[2]), "+f"(d[3])
        : "r"(a[0]), "r"(a[1]), "r"(a[2]), "r"(a[3]), "r"(b0), "r"(b1));
}

#define STAGE_B 20480        // bytes per stage (A 10240 + B 10240), row pitch 80B

// modes: 0 outf=acc; 1 outf = res + acc + dvec[col]*extra;
//        2 outh = half(silu(res)*acc); 3 outf = res + acc
__global__ void __launch_bounds__(256) gemm_f16(
    const __half* __restrict__ A, const __half* __restrict__ Bm,
    int M, int N, int K, float* __restrict__ outf, __half* __restrict__ outh,
    int mode, const float* __restrict__ res,
    const float* __restrict__ extra, const float* __restrict__ dvec)
{
    extern __shared__ __align__(16) char smem[];
    uint32_t smBase = (uint32_t)__cvta_generic_to_shared(smem);
    int tid = threadIdx.x;
    int m0 = blockIdx.y * 128, n0 = blockIdx.x * 128;

    // loader: thread -> row (tid>>1), 2 chunks of 16B
    int lr = tid >> 1, lc = (tid & 1) * 2;
    const __half* Ag = A  + (size_t)(m0 + lr) * K + lc*8;
    const __half* Bg = Bm + (size_t)(n0 + lr) * K + lc*8;
    uint32_t aDst = smBase + lr*80 + lc*16;
    uint32_t bDst = smBase + 10240 + lr*80 + lc*16;

    int lane = tid & 31, warp = tid >> 5;
    int wm = warp & 1, wn = warp >> 1;     // 2x4 warp grid, warp tile 64x32
    int gid = lane >> 2, tig = lane & 3;

    uint32_t aFrag = smBase
        + (uint32_t)(wm*64 + (lane & 7) + ((lane >> 3) & 1)*8) * 80
        + ((lane >> 4) & 1) * 16;
    uint32_t bFrag = smBase + 10240
        + (uint32_t)(wn*32 + ((lane >> 4) & 1)*8 + (lane & 7)) * 80
        + ((lane >> 3) & 1) * 16;

    float acc[4][4][4];
    #pragma unroll
    for (int mt = 0; mt < 4; mt++)
        #pragma unroll
        for (int nt = 0; nt < 4; nt++)
            #pragma unroll
            for (int r = 0; r < 4; r++) acc[mt][nt][r] = 0.f;

    int NT = K >> 5;

    #define LOAD_STAGE(kt, s) do {                                           \
        uint32_t off_ = (uint32_t)(s) * STAGE_B;                             \
        const __half* ga_ = Ag + (size_t)(kt)*32;                            \
        const __half* gb_ = Bg + (size_t)(kt)*32;                            \
        cp16s(aDst + off_,      ga_);                                        \
        cp16s(aDst + off_ + 16, ga_ + 8);                                    \
        cp16s(bDst + off_,      gb_);                                        \
        cp16s(bDst + off_ + 16, gb_ + 8);                                    \
        asm volatile("cp.async.commit_group;\n");                            \
    } while (0)

    LOAD_STAGE(0, 0);
    if (NT > 1) LOAD_STAGE(1, 1);

    int st = 0, ld = 2;
    for (int kt = 0; kt < NT; kt++) {
        if (kt + 1 < NT) asm volatile("cp.async.wait_group 1;\n");
        else             asm volatile("cp.async.wait_group 0;\n");
        __syncthreads();

        if (kt + 2 < NT) {
            LOAD_STAGE(kt + 2, ld);
            ld = (ld == 2) ? 0 : ld + 1;
        }

        uint32_t soff = (uint32_t)st * STAGE_B;
        st = (st == 2) ? 0 : st + 1;

        #pragma unroll
        for (int ks = 0; ks < 2; ks++) {
            uint32_t bb[2][4];
            #pragma unroll
            for (int p = 0; p < 2; p++)
                ldsm4(bb[p][0], bb[p][1], bb[p][2], bb[p][3],
                      bFrag + soff + (uint32_t)p*16*80 + ks*32);
            #pragma unroll
            for (int mt = 0; mt < 4; mt++) {
                uint32_t aa[4];
                ldsm4(aa[0], aa[1], aa[2], aa[3],
                      aFrag + soff + (uint32_t)mt*16*80 + ks*32);
                mma_f16(acc[mt][0], aa, bb[0][0], bb[0][1]);
                mma_f16(acc[mt][1], aa, bb[0][2], bb[0][3]);
                mma_f16(acc[mt][2], aa, bb[1][0], bb[1][1]);
                mma_f16(acc[mt][3], aa, bb[1][2], bb[1][3]);
            }
        }
    }
    #undef LOAD_STAGE

    // epilogue (col-guarded for N < 128 tiles)
    #pragma unroll
    for (int mt = 0; mt < 4; mt++) {
        #pragma unroll
        for (int nt = 0; nt < 4; nt++) {
            int row0 = m0 + wm*64 + mt*16 + gid;
            int col0 = n0 + wn*32 + nt*8 + tig*2;
            if (col0 >= N) continue;
            #pragma unroll
            for (int half = 0; half < 2; half++) {
                int row = row0 + half*8;
                size_t idx = (size_t)row * N + col0;
                float v0 = acc[mt][nt][half*2 + 0];
                float v1 = acc[mt][nt][half*2 + 1];
                if (mode == 1) {
                    float2 r2 = *(const float2*)(res + idx);
                    float2 e2 = *(const float2*)(extra + idx);
                    v0 = r2.x + v0 + dvec[col0]   * e2.x;
                    v1 = r2.y + v1 + dvec[col0+1] * e2.y;
                    *(float2*)(outf + idx) = make_float2(v0, v1);
                } else if (mode == 2) {
                    float2 g2 = *(const float2*)(res + idx);
                    v0 = v0 * (g2.x / (1.f + __expf(-g2.x)));
                    v1 = v1 * (g2.y / (1.f + __expf(-g2.y)));
                    *(__half2*)(outh + idx) = __floats2half2_rn(v0, v1);
                } else if (mode == 3) {
                    float2 r2 = *(const float2*)(res + idx);
                    *(float2*)(outf + idx) = make_float2(v0 + r2.x, v1 + r2.y);
                } else {
                    *(float2*)(outf + idx) = make_float2(v0, v1);
                }
            }
        }
    }
}

// ---------------- launch ----------------
extern "C" void kernel_launch(void* const* d_in, const int* in_sizes, int n_in,
                              void* d_out, int out_size)
{
    const float* x      = (const float*)d_in[0];
    const float* A      = (const float*)d_in[1];
    const float* B      = (const float*)d_in[2];
    const float* C      = (const float*)d_in[3];
    const float* D      = (const float*)d_in[4];
    const float* log_dt = (const float*)d_in[5];
    const float* w_gate = (const float*)d_in[6];
    const float* w_up   = (const float*)d_in[7];
    const float* w_down = (const float*)d_in[8];
    const float* ln1    = (const float*)d_in[9];
    const float* ln2    = (const float*)d_in[10];
    float* out = (float*)d_out;

    float *hn1, *h, *U, *gate;
    __half *hn1h, *hn2h, *acth, *Bbarh, *Ch, *Sh, *wgh, *wuh, *wdh;
    cudaGetSymbolAddress((void**)&hn1,   g_hn1);
    cudaGetSymbolAddress((void**)&hn1h,  g_hn1h);
    cudaGetSymbolAddress((void**)&h,     g_h);
    cudaGetSymbolAddress((void**)&hn2h,  g_hn2h);
    cudaGetSymbolAddress((void**)&U,     g_U);
    cudaGetSymbolAddress((void**)&gate,  g_gate);
    cudaGetSymbolAddress((void**)&acth,  g_acth);
    cudaGetSymbolAddress((void**)&Bbarh, g_Bbarh);
    cudaGetSymbolAddress((void**)&Ch,    g_Ch);
    cudaGetSymbolAddress((void**)&Sh,    g_Sh);
    cudaGetSymbolAddress((void**)&wgh,   g_wgh);
    cudaGetSymbolAddress((void**)&wuh,   g_wuh);
    cudaGetSymbolAddress((void**)&wdh,   g_wdh);

    const int DSMEM = 3 * STAGE_B;   // 61440
    cudaFuncSetAttribute(gemm_f16, cudaFuncAttributeMaxDynamicSharedMemorySize, DSMEM);

    // conversions (independent of SSM path)
    f2h_kernel<<<1024, 256>>>(w_gate, wgh, INTER*HIDDEN/2);
    f2h_kernel<<<1024, 256>>>(w_up,   wuh, INTER*HIDDEN/2);
    f2h_kernel<<<1024, 256>>>(w_down, wdh, HIDDEN*INTER/2);
    f2h_kernel<<<64, 256>>>(C, Ch, HIDDEN*STATE/2);

    // SSM path
    prep_kernel<<<1, 256>>>(A, B, log_dt);
    rmsnorm_kernel<<<ROWS, 256>>>(x, ln1, hn1, hn1h);
    // U = hn1 @ Bbar^T  (M=8192, N=64, K=1024) on tensor cores
    gemm_f16<<<dim3(1, ROWS/128), 256, DSMEM>>>(hn1h, Bbarh, ROWS, STATE, HIDDEN,
                                                U, nullptr, 0, nullptr, nullptr, nullptr);
    local_scan_kernel<<<dim3(NCHUNK, BATCH), 256>>>();
    carry_kernel<<<BATCH, 256>>>();
    fixup_kernel<<<dim3(NCHUNK, BATCH), 256>>>();
    // h = x + S @ C^T + D*hn1  (M=8192, N=1024, K=64)
    gemm_f16<<<dim3(HIDDEN/128, ROWS/128), 256, DSMEM>>>(Sh, Ch, ROWS, HIDDEN, STATE,
                                                         h, nullptr, 1, x, hn1, D);
    // FFN
    rmsnorm_kernel<<<ROWS, 256>>>(h, ln2, nullptr, hn2h);
    gemm_f16<<<dim3(INTER/128, ROWS/128), 256, DSMEM>>>(hn2h, wgh, ROWS, INTER, HIDDEN,
                                                        gate, nullptr, 0, nullptr, nullptr, nullptr);
    gemm_f16<<<dim3(INTER/128, ROWS/128), 256, DSMEM>>>(hn2h, wuh, ROWS, INTER, HIDDEN,
                                                        nullptr, acth, 2, gate, nullptr, nullptr);
    gemm_f16<<<dim3(HIDDEN/128, ROWS/128), 256, DSMEM>>>(acth, wdh, ROWS, HIDDEN, INTER,
                                                         out, nullptr, 3, h, nullptr, nullptr);
}